// round 11
// baseline (speedup 1.0000x reference)
#include <cuda_runtime.h>
#include <math.h>

#define BATCH 8
#define SLEN  2048
#define DIM   512
#define MTOT  (BATCH*SLEN)

// ---------------- scratch ----------------
__device__ float g_qlin[MTOT*DIM];
__device__ float g_klin[MTOT*DIM];
__device__ float g_vlin[MTOT*DIM];
__device__ float g_q[MTOT*DIM];
__device__ float g_k[MTOT*DIM];
__device__ float g_v[MTOT*DIM];
__device__ float g_gate[MTOT*DIM];
__device__ float g_gdn[MTOT*DIM];
__device__ float g_fin[MTOT*DIM];
__device__ float g_alpha[MTOT];
__device__ float g_beta[MTOT];

// ---------------- packed f32x2 helpers ----------------
__device__ __forceinline__ unsigned long long fma2_(unsigned long long a,
                                                    unsigned long long b,
                                                    unsigned long long c) {
    unsigned long long d;
    asm("fma.rn.f32x2 %0, %1, %2, %3;" : "=l"(d) : "l"(a), "l"(b), "l"(c));
    return d;
}
__device__ __forceinline__ unsigned long long mul2_(unsigned long long a,
                                                    unsigned long long b) {
    unsigned long long d;
    asm("mul.rn.f32x2 %0, %1, %2;" : "=l"(d) : "l"(a), "l"(b));
    return d;
}
__device__ __forceinline__ unsigned long long pk2_(float lo, float hi) {
    unsigned long long r;
    asm("mov.b64 %0, {%1, %2};" : "=l"(r)
        : "r"(__float_as_uint(lo)), "r"(__float_as_uint(hi)));
    return r;
}
__device__ __forceinline__ void up2_(unsigned long long a, float& lo, float& hi) {
    unsigned int l, h;
    asm("mov.b64 {%0, %1}, %2;" : "=r"(l), "=r"(h) : "l"(a));
    lo = __uint_as_float(l); hi = __uint_as_float(h);
}
__device__ __forceinline__ float hadd2_(unsigned long long a) {
    float lo, hi; up2_(a, lo, hi); return lo + hi;
}
__device__ __forceinline__ float wredsum_(float v) {
    #pragma unroll
    for (int off = 16; off; off >>= 1) v += __shfl_xor_sync(0xffffffffu, v, off);
    return v;
}
__device__ __forceinline__ float silu_(float x) { return x / (1.0f + __expf(-x)); }
__device__ __forceinline__ void cpasync16_(unsigned int dst, const void* src) {
    asm volatile("cp.async.cg.shared.global [%0], [%1], 16;"
                 :: "r"(dst), "l"(src) : "memory");
}

// ---------------- GEMM: C[M,512] = A @ W^T + bias, optional SiLU ----------------
template<int ACT>
__global__ void __launch_bounds__(256, 2) sgemm_kernel(
    const float* __restrict__ A, const float* __restrict__ W,
    const float* __restrict__ bias, float* __restrict__ C)
{
    __shared__ float As[2][16][140];
    __shared__ float Bs[2][16][140];
    const int tid = threadIdx.x;
    const int m0 = blockIdx.x * 128;
    const int n0 = blockIdx.y * 128;
    const int tx = tid & 15;
    const int ty = tid >> 4;
    const int lrow = tid >> 1;
    const int lcol = (tid & 1) * 8;

    const float* Aptr = A + (size_t)(m0 + lrow) * DIM + lcol;
    const float* Wptr = W + (size_t)(n0 + lrow) * DIM + lcol;

    float4 a0 = *(const float4*)(Aptr + 0);
    float4 a1 = *(const float4*)(Aptr + 4);
    float4 w0 = *(const float4*)(Wptr + 0);
    float4 w1 = *(const float4*)(Wptr + 4);

    unsigned long long acc[8][4];
    #pragma unroll
    for (int i = 0; i < 8; i++)
        #pragma unroll
        for (int j = 0; j < 4; j++) acc[i][j] = 0ULL;

    int buf = 0;
    #pragma unroll 1
    for (int kb = 0; kb < DIM / 16; ++kb) {
        As[buf][lcol+0][lrow] = a0.x; As[buf][lcol+1][lrow] = a0.y;
        As[buf][lcol+2][lrow] = a0.z; As[buf][lcol+3][lrow] = a0.w;
        As[buf][lcol+4][lrow] = a1.x; As[buf][lcol+5][lrow] = a1.y;
        As[buf][lcol+6][lrow] = a1.z; As[buf][lcol+7][lrow] = a1.w;
        Bs[buf][lcol+0][lrow] = w0.x; Bs[buf][lcol+1][lrow] = w0.y;
        Bs[buf][lcol+2][lrow] = w0.z; Bs[buf][lcol+3][lrow] = w0.w;
        Bs[buf][lcol+4][lrow] = w1.x; Bs[buf][lcol+5][lrow] = w1.y;
        Bs[buf][lcol+6][lrow] = w1.z; Bs[buf][lcol+7][lrow] = w1.w;
        __syncthreads();

        if (kb + 1 < DIM / 16) {
            int k0 = (kb + 1) * 16;
            a0 = *(const float4*)(Aptr + k0 + 0);
            a1 = *(const float4*)(Aptr + k0 + 4);
            w0 = *(const float4*)(Wptr + k0 + 0);
            w1 = *(const float4*)(Wptr + k0 + 4);
        }

        const float (*as)[140] = As[buf];
        const float (*bs)[140] = Bs[buf];
        #pragma unroll
        for (int kk = 0; kk < 16; ++kk) {
            float4 af0 = *(const float4*)&as[kk][ty * 8];
            float4 af1 = *(const float4*)&as[kk][ty * 8 + 4];
            float4 bf0 = *(const float4*)&bs[kk][tx * 8];
            float4 bf1 = *(const float4*)&bs[kk][tx * 8 + 4];
            unsigned long long bb[4] = {
                pk2_(bf0.x, bf0.y), pk2_(bf0.z, bf0.w),
                pk2_(bf1.x, bf1.y), pk2_(bf1.z, bf1.w)
            };
            float av[8] = {af0.x, af0.y, af0.z, af0.w, af1.x, af1.y, af1.z, af1.w};
            #pragma unroll
            for (int i = 0; i < 8; i++) {
                unsigned long long am = pk2_(av[i], av[i]);
                #pragma unroll
                for (int j = 0; j < 4; j++)
                    acc[i][j] = fma2_(am, bb[j], acc[i][j]);
            }
        }
        buf ^= 1;
    }

    float4 bs0 = *(const float4*)(bias + n0 + tx * 8);
    float4 bs1 = *(const float4*)(bias + n0 + tx * 8 + 4);
    #pragma unroll
    for (int i = 0; i < 8; i++) {
        float c[8];
        up2_(acc[i][0], c[0], c[1]);
        up2_(acc[i][1], c[2], c[3]);
        up2_(acc[i][2], c[4], c[5]);
        up2_(acc[i][3], c[6], c[7]);
        c[0] += bs0.x; c[1] += bs0.y; c[2] += bs0.z; c[3] += bs0.w;
        c[4] += bs1.x; c[5] += bs1.y; c[6] += bs1.z; c[7] += bs1.w;
        if (ACT == 1) {
            #pragma unroll
            for (int j = 0; j < 8; j++) c[j] = silu_(c[j]);
        }
        float* cp = C + (size_t)(m0 + ty * 8 + i) * DIM + n0 + tx * 8;
        *(float4*)(cp)     = make_float4(c[0], c[1], c[2], c[3]);
        *(float4*)(cp + 4) = make_float4(c[4], c[5], c[6], c[7]);
    }
}

// ---------------- alpha/beta GEMV + sigmoid ----------------
__global__ void __launch_bounds__(256) ab_kernel(
    const float* __restrict__ x,
    const float* __restrict__ Wa, const float* __restrict__ ba,
    const float* __restrict__ Wb, const float* __restrict__ bb,
    float* __restrict__ alpha, float* __restrict__ beta)
{
    const int warp = threadIdx.x >> 5, lane = threadIdx.x & 31;
    const int m = blockIdx.x * 8 + warp;
    const float* xr = x + (size_t)m * DIM;
    float sa = 0.f, sb = 0.f;
    #pragma unroll
    for (int i = 0; i < 4; i++) {
        float4 xv = *(const float4*)(xr + i * 128 + (lane << 2));
        float4 wa = *(const float4*)(Wa + i * 128 + (lane << 2));
        float4 wb = *(const float4*)(Wb + i * 128 + (lane << 2));
        sa += xv.x*wa.x + xv.y*wa.y + xv.z*wa.z + xv.w*wa.w;
        sb += xv.x*wb.x + xv.y*wb.y + xv.z*wb.z + xv.w*wb.w;
    }
    sa = wredsum_(sa);
    sb = wredsum_(sb);
    if (lane == 0) {
        alpha[m] = 1.0f / (1.0f + __expf(-(sa + ba[0])));
        beta[m]  = 1.0f / (1.0f + __expf(-(sb + bb[0])));
    }
}

// ---------------- depthwise causal conv(4) + SiLU (+ optional L2 norm) ----------------
__global__ void __launch_bounds__(128) conv_silu_kernel(
    const float* __restrict__ lin, const float* __restrict__ cw,
    const float* __restrict__ cb, float* __restrict__ outp, int do_l2)
{
    __shared__ float red[4];
    const int m = blockIdx.x;
    const int s = m & (SLEN - 1);
    const int c = threadIdx.x << 2;
    const int lane = threadIdx.x & 31;
    const int warp = threadIdx.x >> 5;

    float w[4][4];
    #pragma unroll
    for (int ch = 0; ch < 4; ++ch) {
        float4 wv = *(const float4*)(cw + (size_t)(c + ch) * 4);
        w[ch][0] = wv.x; w[ch][1] = wv.y; w[ch][2] = wv.z; w[ch][3] = wv.w;
    }
    float4 bv = *(const float4*)(cb + c);
    float y0 = bv.x, y1 = bv.y, y2 = bv.z, y3 = bv.w;
    #pragma unroll
    for (int tau = 0; tau < 4; ++tau) {
        int sp = s - 3 + tau;
        if (sp >= 0) {
            float4 xv = *(const float4*)(lin + (size_t)(m - 3 + tau) * DIM + c);
            y0 += w[0][tau] * xv.x;
            y1 += w[1][tau] * xv.y;
            y2 += w[2][tau] * xv.z;
            y3 += w[3][tau] * xv.w;
        }
    }
    y0 = silu_(y0); y1 = silu_(y1); y2 = silu_(y2); y3 = silu_(y3);
    float sc = 1.0f;
    if (do_l2) {
        float ss = wredsum_(y0*y0 + y1*y1 + y2*y2 + y3*y3);
        if (lane == 0) red[warp] = ss;
        __syncthreads();
        float tot = red[0] + red[1] + red[2] + red[3];
        sc = 1.0f / fmaxf(sqrtf(tot), 1e-12f);
    }
    *(float4*)(outp + (size_t)m * DIM + c) = make_float4(y0*sc, y1*sc, y2*sc, y3*sc);
}

// ---------------- gated delta-rule scan (4 steps fused per iteration) ---------
// 256 CTAs x 128 threads (4 warps, 4 rows/warp), 2 CTAs/SM.
// Per iteration (4 timesteps): ONE barrier, ONE wait, ONE reduction phase.
// Dots on Z_old: zk_j_r, zq_j_r (32) + crosses k_i.k_j (i<j, 6) and
// k_i.q_j (i<=j, 10). Sequential scalar recursion gives w0..w3;
// Z += sum_j w_j * k_j (fused). Outputs o_j = A_j(zq_j + sum w_i ckq_ij).
#define BLANE(v) ((((v)&1)<<4)|(((v)&2)<<2)|((v)&4)|(((v)&8)>>2))
__global__ void __launch_bounds__(128, 2) scan_kernel(
    const float* __restrict__ qn, const float* __restrict__ kn,
    const float* __restrict__ vn, const float* __restrict__ alpha,
    const float* __restrict__ beta, float* __restrict__ outp)
{
    const int tid  = threadIdx.x;
    const int warp = tid >> 5;
    const int lane = tid & 31;
    const int cta  = blockIdx.x;                 // 0..255
    const int b    = cta >> 5;
    const int i0   = ((cta & 31) << 4) + (warp << 2);

    const float* kp = kn + (size_t)b * SLEN * DIM;
    const float* qp = qn + (size_t)b * SLEN * DIM;
    const float* vp = vn + (size_t)b * SLEN * DIM + i0;
    const float* ap = alpha + (size_t)b * SLEN;
    const float* bp = beta  + (size_t)b * SLEN;
    float* op = outp + (size_t)b * SLEN * DIM + i0;

    // smem: 3 buffers x [k0|q0|k1|q1|k2|q2|k3|q3] x 512 floats = 48 KB
    __shared__ __align__(16) float sbuf[3][4096];
    unsigned int sbase = (unsigned int)__cvta_generic_to_shared(sbuf);

    // prologue: iter 0 -> buf0, iter 1 -> buf1 (8 cp.async/thread each)
    #pragma unroll
    for (int it = 0; it < 2; ++it) {
        #pragma unroll
        for (int s = 0; s < 8; s++) {
            const float* src = ((s & 1) ? qp : kp)
                             + (size_t)(4 * it + (s >> 1)) * DIM + tid * 4;
            cpasync16_(sbase + it * 16384 + s * 2048 + tid * 16, src);
        }
        asm volatile("cp.async.commit_group;" ::: "memory");
    }

    unsigned long long z[4][8];
    #pragma unroll
    for (int r = 0; r < 4; r++)
        #pragma unroll
        for (int e = 0; e < 8; e++) z[r][e] = 0ULL;

    float A = 1.0f;
    const unsigned FULL = 0xffffffffu;
    int cur = 0, nxt = 2;

    // output-lane decode: lane holds value v=bitrev5(lane); odd lanes hold zq
    const int idx = (((lane >> 1) & 1) << 3) | (((lane >> 2) & 1) << 2) |
                    (((lane >> 3) & 1) << 1) | ((lane >> 4) & 1);
    const int jj = idx >> 2, rr = idx & 3;
    const bool isout = (lane & 1) != 0;

    #pragma unroll 1
    for (int i = 0; i < SLEN / 4; ++i) {
        asm volatile("cp.async.wait_group 1;" ::: "memory");
        __syncthreads();
        if (i + 2 < SLEN / 4) {
            #pragma unroll
            for (int s = 0; s < 8; s++) {
                const float* src = ((s & 1) ? qp : kp)
                                 + (size_t)(4 * (i + 2) + (s >> 1)) * DIM + tid * 4;
                cpasync16_(sbase + nxt * 16384 + s * 2048 + tid * 16, src);
            }
        }
        asm volatile("cp.async.commit_group;" ::: "memory");

        // load k0..k3 into regs
        unsigned long long kc[4][8];
        #pragma unroll
        for (int j = 0; j < 4; j++) {
            const float4* kf = (const float4*)&sbuf[cur][(2 * j) * 512];
            #pragma unroll
            for (int m = 0; m < 4; m++) {
                float4 u = kf[m * 32 + lane];
                kc[j][2*m] = pk2_(u.x, u.y); kc[j][2*m+1] = pk2_(u.z, u.w);
            }
        }
        float4 v0 = *(const float4*)(vp + (size_t)(4 * i + 0) * DIM);
        float4 v1 = *(const float4*)(vp + (size_t)(4 * i + 1) * DIM);
        float4 v2 = *(const float4*)(vp + (size_t)(4 * i + 2) * DIM);
        float4 v3 = *(const float4*)(vp + (size_t)(4 * i + 3) * DIM);
        float4 av = *(const float4*)(ap + 4 * i);
        float4 bv = *(const float4*)(bp + 4 * i);

        float x[32];   // d[v]: v<16 zk(j*4+r), v>=16 zq
        float cd[16];  // crosses

        // ckk crosses
        {
            unsigned long long a01=0,a02=0,a03=0,a12=0,a13=0,a23=0;
            #pragma unroll
            for (int e = 0; e < 8; e++) {
                a01 = fma2_(kc[0][e], kc[1][e], a01);
                a02 = fma2_(kc[0][e], kc[2][e], a02);
                a03 = fma2_(kc[0][e], kc[3][e], a03);
                a12 = fma2_(kc[1][e], kc[2][e], a12);
                a13 = fma2_(kc[1][e], kc[3][e], a13);
                a23 = fma2_(kc[2][e], kc[3][e], a23);
            }
            cd[0]=hadd2_(a01); cd[1]=hadd2_(a02); cd[2]=hadd2_(a03);
            cd[3]=hadd2_(a12); cd[4]=hadd2_(a13); cd[5]=hadd2_(a23);
        }
        // zk dots
        #pragma unroll
        for (int j = 0; j < 4; j++) {
            unsigned long long t0=0,t1=0,t2=0,t3=0;
            #pragma unroll
            for (int e = 0; e < 8; e++) {
                t0 = fma2_(z[0][e], kc[j][e], t0);
                t1 = fma2_(z[1][e], kc[j][e], t1);
                t2 = fma2_(z[2][e], kc[j][e], t2);
                t3 = fma2_(z[3][e], kc[j][e], t3);
            }
            x[j*4+0]=hadd2_(t0); x[j*4+1]=hadd2_(t1);
            x[j*4+2]=hadd2_(t2); x[j*4+3]=hadd2_(t3);
        }
        // q streaming: zq dots + ckq crosses
        #pragma unroll
        for (int j = 0; j < 4; j++) {
            unsigned long long qb[8];
            const float4* qf = (const float4*)&sbuf[cur][(2 * j + 1) * 512];
            #pragma unroll
            for (int m = 0; m < 4; m++) {
                float4 u = qf[m * 32 + lane];
                qb[2*m] = pk2_(u.x, u.y); qb[2*m+1] = pk2_(u.z, u.w);
            }
            unsigned long long s0=0,s1=0,s2=0,s3=0,c0=0,c1=0,c2=0,c3=0;
            #pragma unroll
            for (int e = 0; e < 8; e++) {
                s0 = fma2_(z[0][e], qb[e], s0);
                s1 = fma2_(z[1][e], qb[e], s1);
                s2 = fma2_(z[2][e], qb[e], s2);
                s3 = fma2_(z[3][e], qb[e], s3);
                c0 = fma2_(kc[0][e], qb[e], c0);
                if (j >= 1) c1 = fma2_(kc[1][e], qb[e], c1);
                if (j >= 2) c2 = fma2_(kc[2][e], qb[e], c2);
                if (j >= 3) c3 = fma2_(kc[3][e], qb[e], c3);
            }
            x[16+j*4+0]=hadd2_(s0); x[16+j*4+1]=hadd2_(s1);
            x[16+j*4+2]=hadd2_(s2); x[16+j*4+3]=hadd2_(s3);
            cd[6+j] = hadd2_(c0);
            if (j >= 1) cd[9+j]  = hadd2_(c1);
            if (j >= 2) cd[11+j] = hadd2_(c2);
            if (j >= 3) cd[12+j] = hadd2_(c3);
        }

        // 32-value packed butterfly -> f = d[bitrev5(lane)]
        float f;
        {
            #pragma unroll
            for (int v = 0; v < 32; v++) x[v] += __shfl_xor_sync(FULL, x[v], 16);
            bool s4 = (lane & 16) != 0;
            float y16[16];
            #pragma unroll
            for (int v = 0; v < 16; v++) y16[v] = s4 ? x[2*v+1] : x[2*v];
            #pragma unroll
            for (int v = 0; v < 16; v++) y16[v] += __shfl_xor_sync(FULL, y16[v], 8);
            bool s3 = (lane & 8) != 0;
            float y8[8];
            #pragma unroll
            for (int v = 0; v < 8; v++) y8[v] = s3 ? y16[2*v+1] : y16[2*v];
            #pragma unroll
            for (int v = 0; v < 8; v++) y8[v] += __shfl_xor_sync(FULL, y8[v], 4);
            bool s2 = (lane & 4) != 0;
            float y4[4];
            #pragma unroll
            for (int v = 0; v < 4; v++) y4[v] = s2 ? y8[2*v+1] : y8[2*v];
            #pragma unroll
            for (int v = 0; v < 4; v++) y4[v] += __shfl_xor_sync(FULL, y4[v], 2);
            bool s1 = (lane & 2) != 0;
            float y2a = s1 ? y4[1] : y4[0];
            float y2b = s1 ? y4[3] : y4[2];
            y2a += __shfl_xor_sync(FULL, y2a, 1);
            y2b += __shfl_xor_sync(FULL, y2b, 1);
            f = (lane & 1) ? y2b : y2a;
        }
        // 16-value crosses butterfly -> e1 = cd[u(lane)] (pairs share)
        float e1;
        {
            #pragma unroll
            for (int v = 0; v < 16; v++) cd[v] += __shfl_xor_sync(FULL, cd[v], 16);
            bool s4 = (lane & 16) != 0;
            float e8[8];
            #pragma unroll
            for (int v = 0; v < 8; v++) e8[v] = s4 ? cd[2*v+1] : cd[2*v];
            #pragma unroll
            for (int v = 0; v < 8; v++) e8[v] += __shfl_xor_sync(FULL, e8[v], 8);
            bool s3 = (lane & 8) != 0;
            float e4[4];
            #pragma unroll
            for (int v = 0; v < 4; v++) e4[v] = s3 ? e8[2*v+1] : e8[2*v];
            #pragma unroll
            for (int v = 0; v < 4; v++) e4[v] += __shfl_xor_sync(FULL, e4[v], 4);
            bool s2 = (lane & 4) != 0;
            float e2a = s2 ? e4[1] : e4[0];
            float e2b = s2 ? e4[3] : e4[2];
            e2a += __shfl_xor_sync(FULL, e2a, 2);
            e2b += __shfl_xor_sync(FULL, e2b, 2);
            float ev = (lane & 2) ? e2b : e2a;
            e1 = ev + __shfl_xor_sync(FULL, ev, 1);
        }

        // broadcasts: zk[j][r] from f, crosses from e1
        float zk[4][4];
        zk[0][0]=__shfl_sync(FULL,f,BLANE(0));  zk[0][1]=__shfl_sync(FULL,f,BLANE(1));
        zk[0][2]=__shfl_sync(FULL,f,BLANE(2));  zk[0][3]=__shfl_sync(FULL,f,BLANE(3));
        zk[1][0]=__shfl_sync(FULL,f,BLANE(4));  zk[1][1]=__shfl_sync(FULL,f,BLANE(5));
        zk[1][2]=__shfl_sync(FULL,f,BLANE(6));  zk[1][3]=__shfl_sync(FULL,f,BLANE(7));
        zk[2][0]=__shfl_sync(FULL,f,BLANE(8));  zk[2][1]=__shfl_sync(FULL,f,BLANE(9));
        zk[2][2]=__shfl_sync(FULL,f,BLANE(10)); zk[2][3]=__shfl_sync(FULL,f,BLANE(11));
        zk[3][0]=__shfl_sync(FULL,f,BLANE(12)); zk[3][1]=__shfl_sync(FULL,f,BLANE(13));
        zk[3][2]=__shfl_sync(FULL,f,BLANE(14)); zk[3][3]=__shfl_sync(FULL,f,BLANE(15));
        float k01=__shfl_sync(FULL,e1,BLANE(0)), k02=__shfl_sync(FULL,e1,BLANE(1));
        float k03=__shfl_sync(FULL,e1,BLANE(2)), k12=__shfl_sync(FULL,e1,BLANE(3));
        float k13=__shfl_sync(FULL,e1,BLANE(4)), k23=__shfl_sync(FULL,e1,BLANE(5));
        float q00=__shfl_sync(FULL,e1,BLANE(6)), q01=__shfl_sync(FULL,e1,BLANE(7));
        float q02=__shfl_sync(FULL,e1,BLANE(8)), q03=__shfl_sync(FULL,e1,BLANE(9));
        float q11=__shfl_sync(FULL,e1,BLANE(10)),q12=__shfl_sync(FULL,e1,BLANE(11));
        float q13=__shfl_sync(FULL,e1,BLANE(12)),q22=__shfl_sync(FULL,e1,BLANE(13));
        float q23=__shfl_sync(FULL,e1,BLANE(14)),q33=__shfl_sync(FULL,e1,BLANE(15));

        // scalar recursion
        float A1 = A * av.x, A2 = A1 * av.y, A3 = A2 * av.z, A4 = A3 * av.w;
        float rA1 = 1.0f/A1, rA2 = 1.0f/A2, rA3 = 1.0f/A3, rA4 = 1.0f/A4;
        float ab0 = av.x*bv.x, ab1 = av.y*bv.y, ab2 = av.z*bv.z, ab3 = av.w*bv.w;
        float vj0[4] = {v0.x, v0.y, v0.z, v0.w};
        float vj1[4] = {v1.x, v1.y, v1.z, v1.w};
        float vj2[4] = {v2.x, v2.y, v2.z, v2.w};
        float vj3[4] = {v3.x, v3.y, v3.z, v3.w};
        float w0[4], w1[4], w2[4], w3[4];
        #pragma unroll
        for (int r = 0; r < 4; r++) {
            w0[r] = (bv.x * vj0[r] - ab0 * (A * zk[0][r])) * rA1;
            float sk1 = A1 * (zk[1][r] + w0[r] * k01);
            w1[r] = (bv.y * vj1[r] - ab1 * sk1) * rA2;
            float sk2 = A2 * (zk[2][r] + w0[r] * k02 + w1[r] * k12);
            w2[r] = (bv.z * vj2[r] - ab2 * sk2) * rA3;
            float sk3 = A3 * (zk[3][r] + w0[r] * k03 + w1[r] * k13 + w2[r] * k23);
            w3[r] = (bv.w * vj3[r] - ab3 * sk3) * rA4;
        }

        // fused state update: Z += w0*k0 + w1*k1 + w2*k2 + w3*k3
        #pragma unroll
        for (int r = 0; r < 4; r++) {
            unsigned long long W0 = pk2_(w0[r], w0[r]);
            unsigned long long W1 = pk2_(w1[r], w1[r]);
            unsigned long long W2 = pk2_(w2[r], w2[r]);
            unsigned long long W3 = pk2_(w3[r], w3[r]);
            #pragma unroll
            for (int e = 0; e < 8; e++)
                z[r][e] = fma2_(W3, kc[3][e],
                          fma2_(W2, kc[2][e],
                          fma2_(W1, kc[1][e],
                          fma2_(W0, kc[0][e], z[r][e]))));
        }

        // outputs (odd lanes hold zq_jj_rr in f)
        {
            float wr0 = rr==0?w0[0]:rr==1?w0[1]:rr==2?w0[2]:w0[3];
            float wr1 = rr==0?w1[0]:rr==1?w1[1]:rr==2?w1[2]:w1[3];
            float wr2 = rr==0?w2[0]:rr==1?w2[1]:rr==2?w2[2]:w2[3];
            float wr3 = rr==0?w3[0]:rr==1?w3[1]:rr==2?w3[2]:w3[3];
            float cq0 = jj==0?q00:jj==1?q01:jj==2?q02:q03;
            float cq1 = jj==1?q11:jj==2?q12:q13;
            float cq2 = jj==2?q22:q23;
            float cq3 = q33;
            float m1 = jj>=1?wr1:0.f, m2 = jj>=2?wr2:0.f, m3 = jj==3?wr3:0.f;
            float Aj = jj==0?A1:jj==1?A2:jj==2?A3:A4;
            float o = Aj*(f + wr0*cq0 + m1*cq1 + m2*cq2 + m3*cq3);
            if (isout)
                op[(size_t)(4*i + jj) * DIM + rr] = o;
        }

        A = A4;
        if ((i & 3) == 3) {
            unsigned long long AA = pk2_(A, A);
            #pragma unroll
            for (int r = 0; r < 4; r++)
                #pragma unroll
                for (int e = 0; e < 8; e++) z[r][e] = mul2_(z[r][e], AA);
            A = 1.0f;
        }

        cur = (cur == 2) ? 0 : cur + 1;
        nxt = (nxt == 2) ? 0 : nxt + 1;
    }
}

// ---------------- zero-centered RMSNorm * gate ----------------
__global__ void __launch_bounds__(128) norm_gate_kernel(
    const float* __restrict__ gdn, const float* __restrict__ norm_w,
    const float* __restrict__ gate, float* __restrict__ fin)
{
    __shared__ float rs[4], rq[4];
    const int m = blockIdx.x;
    const int c = threadIdx.x << 2;
    const int lane = threadIdx.x & 31;
    const int warp = threadIdx.x >> 5;

    float4 xv = *(const float4*)(gdn + (size_t)m * DIM + c);
    float s = wredsum_(xv.x + xv.y + xv.z + xv.w);
    float q = wredsum_(xv.x*xv.x + xv.y*xv.y + xv.z*xv.z + xv.w*xv.w);
    if (lane == 0) { rs[warp] = s; rq[warp] = q; }
    __syncthreads();
    float sum = rs[0] + rs[1] + rs[2] + rs[3];
    float sq  = rq[0] + rq[1] + rq[2] + rq[3];
    float mean = sum * (1.0f / DIM);
    float var  = sq * (1.0f / DIM) - mean * mean;
    float inv  = rsqrtf(var + 1e-5f);

    float4 wv = *(const float4*)(norm_w + c);
    float4 gv = *(const float4*)(gate + (size_t)m * DIM + c);
    float4 r;
    r.x = (xv.x - mean) * inv * wv.x * gv.x;
    r.y = (xv.y - mean) * inv * wv.y * gv.y;
    r.z = (xv.z - mean) * inv * wv.z * gv.z;
    r.w = (xv.w - mean) * inv * wv.w * gv.w;
    *(float4*)(fin + (size_t)m * DIM + c) = r;
}

// ---------------- launch ----------------
extern "C" void kernel_launch(void* const* d_in, const int* in_sizes, int n_in,
                              void* d_out, int out_size) {
    const float* x    = (const float*)d_in[0];
    const float* Wq   = (const float*)d_in[1];
    const float* bq   = (const float*)d_in[2];
    const float* Wk   = (const float*)d_in[3];
    const float* bk   = (const float*)d_in[4];
    const float* Wv   = (const float*)d_in[5];
    const float* bv   = (const float*)d_in[6];
    const float* Wa   = (const float*)d_in[7];
    const float* ba   = (const float*)d_in[8];
    const float* Wb   = (const float*)d_in[9];
    const float* bb   = (const float*)d_in[10];
    const float* cwq  = (const float*)d_in[11];
    const float* cbq  = (const float*)d_in[12];
    const float* cwk  = (const float*)d_in[13];
    const float* cbk  = (const float*)d_in[14];
    const float* cwv  = (const float*)d_in[15];
    const float* cbv  = (const float*)d_in[16];
    const float* norm_w = (const float*)d_in[17];
    const float* Wg   = (const float*)d_in[18];
    const float* bg   = (const float*)d_in[19];
    const float* Wo   = (const float*)d_in[20];
    const float* bo   = (const float*)d_in[21];
    float* out = (float*)d_out;

    float *qlin, *klin, *vlin, *qn, *kn, *vn, *gate, *gdn, *fin, *al, *be;
    cudaGetSymbolAddress((void**)&qlin, g_qlin);
    cudaGetSymbolAddress((void**)&klin, g_klin);
    cudaGetSymbolAddress((void**)&vlin, g_vlin);
    cudaGetSymbolAddress((void**)&qn,   g_q);
    cudaGetSymbolAddress((void**)&kn,   g_k);
    cudaGetSymbolAddress((void**)&vn,   g_v);
    cudaGetSymbolAddress((void**)&gate, g_gate);
    cudaGetSymbolAddress((void**)&gdn,  g_gdn);
    cudaGetSymbolAddress((void**)&fin,  g_fin);
    cudaGetSymbolAddress((void**)&al,   g_alpha);
    cudaGetSymbolAddress((void**)&be,   g_beta);

    dim3 gg(MTOT / 128, DIM / 128);
    sgemm_kernel<0><<<gg, 256>>>(x, Wq, bq, qlin);
    sgemm_kernel<0><<<gg, 256>>>(x, Wk, bk, klin);
    sgemm_kernel<0><<<gg, 256>>>(x, Wv, bv, vlin);
    sgemm_kernel<1><<<gg, 256>>>(x, Wg, bg, gate);
    ab_kernel<<<MTOT / 8, 256>>>(x, Wa, ba, Wb, bb, al, be);

    conv_silu_kernel<<<MTOT, 128>>>(qlin, cwq, cbq, qn, 1);
    conv_silu_kernel<<<MTOT, 128>>>(klin, cwk, cbk, kn, 1);
    conv_silu_kernel<<<MTOT, 128>>>(vlin, cwv, cbv, vn, 0);

    scan_kernel<<<256, 128>>>(qn, kn, vn, al, be, gdn);

    norm_gate_kernel<<<MTOT, 128>>>(gdn, norm_w, gate, fin);
    sgemm_kernel<0><<<gg, 256>>>(fin, Wo, bo, out);
}

// round 14
// speedup vs baseline: 1.4084x; 1.4084x over previous
#include <cuda_runtime.h>
#include <cuda_bf16.h>
#include <math.h>

#define BATCH 8
#define SLEN  2048
#define DIM   512
#define MTOT  (BATCH*SLEN)

// ---------------- scratch ----------------
__device__ float g_qlin[MTOT*DIM];
__device__ float g_klin[MTOT*DIM];
__device__ float g_vlin[MTOT*DIM];
__device__ float g_q[MTOT*DIM];
__device__ float g_k[MTOT*DIM];
__device__ float g_v[MTOT*DIM];
__device__ float g_gate[MTOT*DIM];
__device__ float g_gdn[MTOT*DIM];
__device__ float g_alpha[MTOT];
__device__ float g_beta[MTOT];
__device__ __align__(16) __nv_bfloat16 g_xhi[MTOT*DIM];
__device__ __align__(16) __nv_bfloat16 g_xlo[MTOT*DIM];
__device__ __align__(16) __nv_bfloat16 g_fhi[MTOT*DIM];
__device__ __align__(16) __nv_bfloat16 g_flo[MTOT*DIM];
__device__ __align__(16) __nv_bfloat16 g_whi[5*DIM*DIM];
__device__ __align__(16) __nv_bfloat16 g_wlo[5*DIM*DIM];

// ---------------- helpers ----------------
__device__ __forceinline__ unsigned long long fma2_(unsigned long long a,
                                                    unsigned long long b,
                                                    unsigned long long c) {
    unsigned long long d;
    asm("fma.rn.f32x2 %0, %1, %2, %3;" : "=l"(d) : "l"(a), "l"(b), "l"(c));
    return d;
}
__device__ __forceinline__ unsigned long long mul2_(unsigned long long a,
                                                    unsigned long long b) {
    unsigned long long d;
    asm("mul.rn.f32x2 %0, %1, %2;" : "=l"(d) : "l"(a), "l"(b));
    return d;
}
__device__ __forceinline__ unsigned long long pk2_(float lo, float hi) {
    unsigned long long r;
    asm("mov.b64 %0, {%1, %2};" : "=l"(r)
        : "r"(__float_as_uint(lo)), "r"(__float_as_uint(hi)));
    return r;
}
__device__ __forceinline__ float hadd2_(unsigned long long a) {
    unsigned int l, h;
    asm("mov.b64 {%0, %1}, %2;" : "=r"(l), "=r"(h) : "l"(a));
    return __uint_as_float(l) + __uint_as_float(h);
}
__device__ __forceinline__ float wredsum_(float v) {
    #pragma unroll
    for (int off = 16; off; off >>= 1) v += __shfl_xor_sync(0xffffffffu, v, off);
    return v;
}
__device__ __forceinline__ float silu_(float x) { return x / (1.0f + __expf(-x)); }
__device__ __forceinline__ void cpasync16_(unsigned int dst, const void* src) {
    asm volatile("cp.async.cg.shared.global [%0], [%1], 16;"
                 :: "r"(dst), "l"(src) : "memory");
}
__device__ __forceinline__ unsigned int smem_u32_(const void* p) {
    unsigned int a;
    asm("{ .reg .u64 t; cvta.to.shared.u64 t, %1; cvt.u32.u64 %0, t; }"
        : "=r"(a) : "l"(p));
    return a;
}
__device__ __forceinline__ void ldsm4_(unsigned& r0, unsigned& r1, unsigned& r2,
                                       unsigned& r3, unsigned addr) {
    asm volatile("ldmatrix.sync.aligned.m8n8.x4.shared.b16 {%0,%1,%2,%3}, [%4];"
                 : "=r"(r0), "=r"(r1), "=r"(r2), "=r"(r3) : "r"(addr));
}
__device__ __forceinline__ void mma16816_(float* d, const unsigned* a,
                                          const unsigned* b) {
    asm volatile(
        "mma.sync.aligned.m16n8k16.row.col.f32.bf16.bf16.f32 "
        "{%0,%1,%2,%3}, {%4,%5,%6,%7}, {%8,%9}, {%0,%1,%2,%3};"
        : "+f"(d[0]), "+f"(d[1]), "+f"(d[2]), "+f"(d[3])
        : "r"(a[0]), "r"(a[1]), "r"(a[2]), "r"(a[3]), "r"(b[0]), "r"(b[1]));
}

// ---------------- fp32 -> bf16 hi/lo split ----------------
__global__ void __launch_bounds__(256) convert_split_kernel(
    const float* __restrict__ src, __nv_bfloat16* __restrict__ hi,
    __nv_bfloat16* __restrict__ lo, int n4)
{
    int i = blockIdx.x * 256 + threadIdx.x;
    if (i >= n4) return;
    float4 v = ((const float4*)src)[i];
    __nv_bfloat16 h0 = __float2bfloat16(v.x);
    __nv_bfloat16 h1 = __float2bfloat16(v.y);
    __nv_bfloat16 h2 = __float2bfloat16(v.z);
    __nv_bfloat16 h3 = __float2bfloat16(v.w);
    __nv_bfloat16 l0 = __float2bfloat16(v.x - __bfloat162float(h0));
    __nv_bfloat16 l1 = __float2bfloat16(v.y - __bfloat162float(h1));
    __nv_bfloat16 l2 = __float2bfloat16(v.z - __bfloat162float(h2));
    __nv_bfloat16 l3 = __float2bfloat16(v.w - __bfloat162float(h3));
    __nv_bfloat162 ph0; ph0.x = h0; ph0.y = h1;
    __nv_bfloat162 ph1; ph1.x = h2; ph1.y = h3;
    __nv_bfloat162 pl0; pl0.x = l0; pl0.y = l1;
    __nv_bfloat162 pl1; pl1.x = l2; pl1.y = l3;
    ((__nv_bfloat162*)hi)[2*i]   = ph0;
    ((__nv_bfloat162*)hi)[2*i+1] = ph1;
    ((__nv_bfloat162*)lo)[2*i]   = pl0;
    ((__nv_bfloat162*)lo)[2*i+1] = pl1;
}

// ---------------- mma.sync bf16-split GEMM: C = A @ W^T + bias (+SiLU) -------
// CTA 128x128, 256 threads (8 warps: 4 in M x 2 in N, warp tile 32x64).
// K-chunks of 32, double-buffered cp.async. 3 products: AhBh + AhBl + AlBh.
// W stored [n][k] (k contiguous) -> B fragment via NON-transposed ldmatrix
// (thread t gets W[n=t/4][k=2(t%4)+i] = required B[k][n] layout).
#define GROW 80           // bytes per smem row (32 bf16 + 8 pad)
#define TILEB (128*GROW)  // 10240 bytes per tile
template<int ACT>
__global__ void __launch_bounds__(256) gemm_mma(
    const __nv_bfloat16* __restrict__ Ah, const __nv_bfloat16* __restrict__ Al,
    const __nv_bfloat16* __restrict__ Wh, const __nv_bfloat16* __restrict__ Wl,
    const float* __restrict__ bias, float* __restrict__ C)
{
    extern __shared__ char dsm[];      // 2 * 4 * TILEB = 81920 bytes
    const int tid  = threadIdx.x;
    const int wid  = tid >> 5;
    const int lane = tid & 31;
    const int wm = wid >> 1;           // 0..3
    const int wn = wid & 1;            // 0..1
    const int m0 = blockIdx.x * 128;
    const int n0 = blockIdx.y * 128;

    unsigned int sb = smem_u32_(dsm);
    const __nv_bfloat16* gsrc[4] = {Ah, Al, Wh, Wl};
    const int gbase[4] = {m0, m0, n0, n0};

    // stage chunk kc into buffer buf (no commit; caller commits)
    auto stage = [&](int kc, int buf) {
        unsigned int bb = sb + buf * (4 * TILEB);
        #pragma unroll
        for (int it = 0; it < 8; it++) {
            int i = tid + it * 256;           // 0..2047
            int tile = i >> 9;                // 0..3
            int j = i & 511;
            int row = j >> 2, seg = j & 3;
            cpasync16_(bb + tile * TILEB + row * GROW + seg * 16,
                       gsrc[tile] + (size_t)(gbase[tile] + row) * DIM + kc * 32 + seg * 8);
        }
    };

    stage(0, 0);
    asm volatile("cp.async.commit_group;" ::: "memory");

    float acc[2][8][4];
    #pragma unroll
    for (int mt = 0; mt < 2; mt++)
        #pragma unroll
        for (int nt = 0; nt < 8; nt++)
            #pragma unroll
            for (int c = 0; c < 4; c++) acc[mt][nt][c] = 0.f;

    // ldmatrix lane addressing
    const int arow = wm * 32 + (lane & 15);
    const int acol = (lane >> 4) * 16;               // bytes (8 bf16)
    const int brow = wn * 64 + (lane & 7) + (((lane >> 4) & 1) << 3);
    const int bcol = ((lane >> 3) & 1) * 16;         // bytes

    #pragma unroll 1
    for (int kc = 0; kc < 16; ++kc) {
        if (kc + 1 < 16) stage(kc + 1, (kc + 1) & 1);
        asm volatile("cp.async.commit_group;" ::: "memory");  // may be empty at tail
        asm volatile("cp.async.wait_group 1;" ::: "memory");
        __syncthreads();
        unsigned int bb = sb + (kc & 1) * (4 * TILEB);
        unsigned int tAh = bb, tAl = bb + TILEB, tWh = bb + 2*TILEB, tWl = bb + 3*TILEB;

        #pragma unroll
        for (int ks = 0; ks < 2; ks++) {
            unsigned ah[2][4], al[2][4];
            #pragma unroll
            for (int mt = 0; mt < 2; mt++) {
                unsigned aoff = (arow + mt * 16) * GROW + ks * 32 + acol;
                ldsm4_(ah[mt][0], ah[mt][1], ah[mt][2], ah[mt][3], tAh + aoff);
                ldsm4_(al[mt][0], al[mt][1], al[mt][2], al[mt][3], tAl + aoff);
            }
            // B tiles (no trans): r0=(n0-7,k0-7), r1=(n0-7,k8-15),
            //                     r2=(n8-15,k0-7), r3=(n8-15,k8-15)
            unsigned bh[4][4], bl[4][4];
            #pragma unroll
            for (int p = 0; p < 4; p++) {
                unsigned boff = (brow + p * 16) * GROW + ks * 32 + bcol;
                ldsm4_(bh[p][0], bh[p][1], bh[p][2], bh[p][3], tWh + boff);
                ldsm4_(bl[p][0], bl[p][1], bl[p][2], bl[p][3], tWl + boff);
            }
            #pragma unroll
            for (int mt = 0; mt < 2; mt++)
                #pragma unroll
                for (int nt = 0; nt < 8; nt++) {
                    const unsigned* bph = &bh[nt >> 1][(nt & 1) * 2];
                    const unsigned* bpl = &bl[nt >> 1][(nt & 1) * 2];
                    mma16816_(acc[mt][nt], ah[mt], bph);
                    mma16816_(acc[mt][nt], ah[mt], bpl);
                    mma16816_(acc[mt][nt], al[mt], bph);
                }
        }
        __syncthreads();
    }

    // epilogue
    const int g = lane >> 2;
    const int cc = (lane & 3) * 2;
    #pragma unroll
    for (int mt = 0; mt < 2; mt++) {
        #pragma unroll
        for (int nt = 0; nt < 8; nt++) {
            int col = n0 + wn * 64 + nt * 8 + cc;
            float2 bv = *(const float2*)(bias + col);
            int row0 = m0 + wm * 32 + mt * 16 + g;
            float c0 = acc[mt][nt][0] + bv.x;
            float c1 = acc[mt][nt][1] + bv.y;
            float c2 = acc[mt][nt][2] + bv.x;
            float c3 = acc[mt][nt][3] + bv.y;
            if (ACT == 1) { c0 = silu_(c0); c1 = silu_(c1); c2 = silu_(c2); c3 = silu_(c3); }
            *(float2*)(C + (size_t)row0 * DIM + col)       = make_float2(c0, c1);
            *(float2*)(C + (size_t)(row0 + 8) * DIM + col) = make_float2(c2, c3);
        }
    }
}

// ---------------- alpha/beta GEMV + sigmoid ----------------
__global__ void __launch_bounds__(256) ab_kernel(
    const float* __restrict__ x,
    const float* __restrict__ Wa, const float* __restrict__ ba,
    const float* __restrict__ Wb, const float* __restrict__ bb,
    float* __restrict__ alpha, float* __restrict__ beta)
{
    const int warp = threadIdx.x >> 5, lane = threadIdx.x & 31;
    const int m = blockIdx.x * 8 + warp;
    const float* xr = x + (size_t)m * DIM;
    float sa = 0.f, sb = 0.f;
    #pragma unroll
    for (int i = 0; i < 4; i++) {
        float4 xv = *(const float4*)(xr + i * 128 + (lane << 2));
        float4 wa = *(const float4*)(Wa + i * 128 + (lane << 2));
        float4 wb = *(const float4*)(Wb + i * 128 + (lane << 2));
        sa += xv.x*wa.x + xv.y*wa.y + xv.z*wa.z + xv.w*wa.w;
        sb += xv.x*wb.x + xv.y*wb.y + xv.z*wb.z + xv.w*wb.w;
    }
    sa = wredsum_(sa);
    sb = wredsum_(sb);
    if (lane == 0) {
        alpha[m] = 1.0f / (1.0f + __expf(-(sa + ba[0])));
        beta[m]  = 1.0f / (1.0f + __expf(-(sb + bb[0])));
    }
}

// ---------------- depthwise causal conv(4) + SiLU (+ optional L2 norm) -------
__global__ void __launch_bounds__(128) conv_silu_kernel(
    const float* __restrict__ lin, const float* __restrict__ cw,
    const float* __restrict__ cb, float* __restrict__ outp, int do_l2)
{
    __shared__ float red[4];
    const int m = blockIdx.x;
    const int s = m & (SLEN - 1);
    const int c = threadIdx.x << 2;
    const int lane = threadIdx.x & 31;
    const int warp = threadIdx.x >> 5;

    float w[4][4];
    #pragma unroll
    for (int ch = 0; ch < 4; ++ch) {
        float4 wv = *(const float4*)(cw + (size_t)(c + ch) * 4);
        w[ch][0] = wv.x; w[ch][1] = wv.y; w[ch][2] = wv.z; w[ch][3] = wv.w;
    }
    float4 bv = *(const float4*)(cb + c);
    float y0 = bv.x, y1 = bv.y, y2 = bv.z, y3 = bv.w;
    #pragma unroll
    for (int tau = 0; tau < 4; ++tau) {
        int sp = s - 3 + tau;
        if (sp >= 0) {
            float4 xv = *(const float4*)(lin + (size_t)(m - 3 + tau) * DIM + c);
            y0 += w[0][tau] * xv.x;
            y1 += w[1][tau] * xv.y;
            y2 += w[2][tau] * xv.z;
            y3 += w[3][tau] * xv.w;
        }
    }
    y0 = silu_(y0); y1 = silu_(y1); y2 = silu_(y2); y3 = silu_(y3);
    float sc = 1.0f;
    if (do_l2) {
        float ss = wredsum_(y0*y0 + y1*y1 + y2*y2 + y3*y3);
        if (lane == 0) red[warp] = ss;
        __syncthreads();
        float tot = red[0] + red[1] + red[2] + red[3];
        sc = 1.0f / fmaxf(sqrtf(tot), 1e-12f);
    }
    *(float4*)(outp + (size_t)m * DIM + c) = make_float4(y0*sc, y1*sc, y2*sc, y3*sc);
}

// ---------------- gated delta-rule scan (2 steps fused; R10 version) ---------
__global__ void __launch_bounds__(128, 2) scan_kernel(
    const float* __restrict__ qn, const float* __restrict__ kn,
    const float* __restrict__ vn, const float* __restrict__ alpha,
    const float* __restrict__ beta, float* __restrict__ outp)
{
    const int warp = threadIdx.x >> 5;
    const int lane = threadIdx.x & 31;
    const int cta  = blockIdx.x;
    const int b    = cta >> 5;
    const int i0   = ((cta & 31) << 4) + (warp << 2);

    const float* kp = kn + (size_t)b * SLEN * DIM;
    const float* qp = qn + (size_t)b * SLEN * DIM;
    const float* vp = vn + (size_t)b * SLEN * DIM + i0;
    const float* ap = alpha + (size_t)b * SLEN;
    const float* bp = beta  + (size_t)b * SLEN;
    float* op = outp + (size_t)b * SLEN * DIM + i0;

    __shared__ __align__(16) float sbuf[3][2048];
    unsigned int sbase = smem_u32_(sbuf);
    const float* gsec = ((warp & 1) ? qp : kp) + (warp >> 1) * DIM;
    const unsigned int soff = warp * 2048 + lane * 16;

    #pragma unroll
    for (int m = 0; m < 4; m++)
        cpasync16_(sbase + soff + m * 512, gsec + (lane + 32 * m) * 4);
    asm volatile("cp.async.commit_group;" ::: "memory");
    #pragma unroll
    for (int m = 0; m < 4; m++)
        cpasync16_(sbase + 8192 + soff + m * 512, gsec + 2 * DIM + (lane + 32 * m) * 4);
    asm volatile("cp.async.commit_group;" ::: "memory");

    unsigned long long z[4][8];
    #pragma unroll
    for (int r = 0; r < 4; r++)
        #pragma unroll
        for (int e = 0; e < 8; e++) z[r][e] = 0ULL;

    float A = 1.0f;
    const unsigned FULL = 0xffffffffu;
    int cur = 0, nxt = 2;

    const bool isout = (lane & 3) == 2;
    const int ostep = (lane >> 2) & 1;
    const int orow = ((lane >> 4) & 1) + (((lane >> 3) & 1) << 1);

    #pragma unroll 1
    for (int i = 0; i < SLEN / 2; ++i) {
        asm volatile("cp.async.wait_group 1;" ::: "memory");
        __syncthreads();
        if (i + 2 < SLEN / 2) {
            const float* gs2 = gsec + (size_t)(2 * i + 4) * DIM;
            #pragma unroll
            for (int m = 0; m < 4; m++)
                cpasync16_(sbase + nxt * 8192 + soff + m * 512, gs2 + (lane + 32 * m) * 4);
        }
        asm volatile("cp.async.commit_group;" ::: "memory");

        unsigned long long kc0[8], qc0[8], kc1[8], qc1[8];
        {
            const float4* f0 = (const float4*)&sbuf[cur][0];
            const float4* f1 = (const float4*)&sbuf[cur][512];
            const float4* f2 = (const float4*)&sbuf[cur][1024];
            const float4* f3 = (const float4*)&sbuf[cur][1536];
            #pragma unroll
            for (int m = 0; m < 4; m++) {
                float4 u;
                u = f0[m * 32 + lane]; kc0[2*m] = pk2_(u.x,u.y); kc0[2*m+1] = pk2_(u.z,u.w);
                u = f1[m * 32 + lane]; qc0[2*m] = pk2_(u.x,u.y); qc0[2*m+1] = pk2_(u.z,u.w);
                u = f2[m * 32 + lane]; kc1[2*m] = pk2_(u.x,u.y); kc1[2*m+1] = pk2_(u.z,u.w);
                u = f3[m * 32 + lane]; qc1[2*m] = pk2_(u.x,u.y); qc1[2*m+1] = pk2_(u.z,u.w);
            }
        }
        float4 v0 = *(const float4*)(vp + (size_t)(2 * i) * DIM);
        float4 v1 = *(const float4*)(vp + (size_t)(2 * i + 1) * DIM);
        float2 a2 = *(const float2*)(ap + 2 * i);
        float2 b2 = *(const float2*)(bp + 2 * i);

        unsigned long long zka[4] = {0,0,0,0}, zqa[4] = {0,0,0,0};
        unsigned long long zkb[4] = {0,0,0,0}, zqb[4] = {0,0,0,0};
        unsigned long long c00a = 0, c01a = 0, cka = 0, c11a = 0;
        #pragma unroll
        for (int e = 0; e < 8; e++) {
            #pragma unroll
            for (int r = 0; r < 4; r++) {
                zka[r] = fma2_(z[r][e], kc0[e], zka[r]);
                zqa[r] = fma2_(z[r][e], qc0[e], zqa[r]);
                zkb[r] = fma2_(z[r][e], kc1[e], zkb[r]);
                zqb[r] = fma2_(z[r][e], qc1[e], zqb[r]);
            }
            c00a = fma2_(kc0[e], qc0[e], c00a);
            c01a = fma2_(kc0[e], qc1[e], c01a);
            cka  = fma2_(kc0[e], kc1[e], cka);
            c11a = fma2_(kc1[e], qc1[e], c11a);
        }
        float d[16];
        d[0]=hadd2_(zka[0]); d[1]=hadd2_(zka[1]); d[2]=hadd2_(zka[2]); d[3]=hadd2_(zka[3]);
        d[4]=hadd2_(zkb[0]); d[5]=hadd2_(zkb[1]); d[6]=hadd2_(zkb[2]); d[7]=hadd2_(zkb[3]);
        d[8]=hadd2_(zqa[0]); d[9]=hadd2_(zqa[1]); d[10]=hadd2_(zqa[2]); d[11]=hadd2_(zqa[3]);
        d[12]=hadd2_(zqb[0]); d[13]=hadd2_(zqb[1]); d[14]=hadd2_(zqb[2]); d[15]=hadd2_(zqb[3]);
        float f;
        {
            float x[16];
            #pragma unroll
            for (int j = 0; j < 16; j++) x[j] = d[j] + __shfl_xor_sync(FULL, d[j], 16);
            bool s4 = (lane & 16) != 0;
            float w8[8];
            #pragma unroll
            for (int j = 0; j < 8; j++) w8[j] = s4 ? x[2*j+1] : x[2*j];
            float y8[8];
            #pragma unroll
            for (int j = 0; j < 8; j++) y8[j] = w8[j] + __shfl_xor_sync(FULL, w8[j], 8);
            bool s3 = (lane & 8) != 0;
            float u4[4];
            #pragma unroll
            for (int j = 0; j < 4; j++) u4[j] = s3 ? y8[2*j+1] : y8[2*j];
            float t4[4];
            #pragma unroll
            for (int j = 0; j < 4; j++) t4[j] = u4[j] + __shfl_xor_sync(FULL, u4[j], 4);
            bool s2 = (lane & 4) != 0;
            float sv[2];
            sv[0] = s2 ? t4[1] : t4[0];
            sv[1] = s2 ? t4[3] : t4[2];
            float rv[2];
            rv[0] = sv[0] + __shfl_xor_sync(FULL, sv[0], 2);
            rv[1] = sv[1] + __shfl_xor_sync(FULL, sv[1], 2);
            float qv = (lane & 2) ? rv[1] : rv[0];
            f = qv + __shfl_xor_sync(FULL, qv, 1);
        }
        float c00, c01, ck, c11;
        {
            float e0 = hadd2_(c00a), e1 = hadd2_(c01a), e2 = hadd2_(cka), e3 = hadd2_(c11a);
            float x0 = e0 + __shfl_xor_sync(FULL, e0, 16);
            float x1 = e1 + __shfl_xor_sync(FULL, e1, 16);
            float x2 = e2 + __shfl_xor_sync(FULL, e2, 16);
            float x3 = e3 + __shfl_xor_sync(FULL, e3, 16);
            bool s4 = (lane & 16) != 0;
            float g0 = s4 ? x1 : x0;
            float g1 = s4 ? x3 : x2;
            float y0 = g0 + __shfl_xor_sync(FULL, g0, 8);
            float y1 = g1 + __shfl_xor_sync(FULL, g1, 8);
            float h = (lane & 8) ? y1 : y0;
            h += __shfl_xor_sync(FULL, h, 4);
            h += __shfl_xor_sync(FULL, h, 2);
            h += __shfl_xor_sync(FULL, h, 1);
            c00 = __shfl_sync(FULL, h, 0);
            c01 = __shfl_sync(FULL, h, 16);
            ck  = __shfl_sync(FULL, h, 8);
            c11 = __shfl_sync(FULL, h, 24);
        }
        float zk0r[4], zk1r[4];
        zk0r[0] = __shfl_sync(FULL, f, 0);
        zk0r[1] = __shfl_sync(FULL, f, 16);
        zk0r[2] = __shfl_sync(FULL, f, 8);
        zk0r[3] = __shfl_sync(FULL, f, 24);
        zk1r[0] = __shfl_sync(FULL, f, 4);
        zk1r[1] = __shfl_sync(FULL, f, 20);
        zk1r[2] = __shfl_sync(FULL, f, 12);
        zk1r[3] = __shfl_sync(FULL, f, 28);

        float A1 = A * a2.x;
        float rA1 = 1.0f / A1;
        float ab0 = a2.x * b2.x;
        float vv0[4] = {v0.x, v0.y, v0.z, v0.w};
        float vv1[4] = {v1.x, v1.y, v1.z, v1.w};
        float w0v[4], w1v[4];
        #pragma unroll
        for (int r = 0; r < 4; r++)
            w0v[r] = (b2.x * vv0[r] - ab0 * (A * zk0r[r])) * rA1;
        float A2f = A1 * a2.y;
        float rA2 = 1.0f / A2f;
        float ab1 = a2.y * b2.y;
        #pragma unroll
        for (int r = 0; r < 4; r++) {
            float sk1 = A1 * (zk1r[r] + w0v[r] * ck);
            w1v[r] = (b2.y * vv1[r] - ab1 * sk1) * rA2;
        }

        #pragma unroll
        for (int r = 0; r < 4; r++) {
            unsigned long long W0 = pk2_(w0v[r], w0v[r]);
            unsigned long long W1 = pk2_(w1v[r], w1v[r]);
            #pragma unroll
            for (int e = 0; e < 8; e++)
                z[r][e] = fma2_(W1, kc1[e], fma2_(W0, kc0[e], z[r][e]));
        }

        if (isout) {
            float o;
            if (ostep == 0) o = A1 * (f + w0v[orow] * c00);
            else            o = A2f * (f + w0v[orow] * c01 + w1v[orow] * c11);
            op[(size_t)(2 * i + ostep) * DIM + orow] = o;
        }

        A = A2f;
        if ((i & 7) == 7) {
            unsigned long long AA = pk2_(A, A);
            #pragma unroll
            for (int r = 0; r < 4; r++)
                #pragma unroll
                for (int e = 0; e < 8; e++) z[r][e] = mul2_(z[r][e], AA);
            A = 1.0f;
        }

        cur = (cur == 2) ? 0 : cur + 1;
        nxt = (nxt == 2) ? 0 : nxt + 1;
    }
}

// ---------------- zero-centered RMSNorm * gate -> bf16 hi/lo split -----------
__global__ void __launch_bounds__(128) norm_gate_kernel(
    const float* __restrict__ gdn, const float* __restrict__ norm_w,
    const float* __restrict__ gate,
    __nv_bfloat16* __restrict__ fhi, __nv_bfloat16* __restrict__ flo)
{
    __shared__ float rs[4], rq[4];
    const int m = blockIdx.x;
    const int c = threadIdx.x << 2;
    const int lane = threadIdx.x & 31;
    const int warp = threadIdx.x >> 5;

    float4 xv = *(const float4*)(gdn + (size_t)m * DIM + c);
    float s = wredsum_(xv.x + xv.y + xv.z + xv.w);
    float q = wredsum_(xv.x*xv.x + xv.y*xv.y + xv.z*xv.z + xv.w*xv.w);
    if (lane == 0) { rs[warp] = s; rq[warp] = q; }
    __syncthreads();
    float sum = rs[0] + rs[1] + rs[2] + rs[3];
    float sq  = rq[0] + rq[1] + rq[2] + rq[3];
    float mean = sum * (1.0f / DIM);
    float var  = sq * (1.0f / DIM) - mean * mean;
    float inv  = rsqrtf(var + 1e-5f);

    float4 wv = *(const float4*)(norm_w + c);
    float4 gv = *(const float4*)(gate + (size_t)m * DIM + c);
    float r0 = (xv.x - mean) * inv * wv.x * gv.x;
    float r1 = (xv.y - mean) * inv * wv.y * gv.y;
    float r2 = (xv.z - mean) * inv * wv.z * gv.z;
    float r3 = (xv.w - mean) * inv * wv.w * gv.w;

    __nv_bfloat16 h0 = __float2bfloat16(r0), h1 = __float2bfloat16(r1);
    __nv_bfloat16 h2 = __float2bfloat16(r2), h3 = __float2bfloat16(r3);
    __nv_bfloat16 l0 = __float2bfloat16(r0 - __bfloat162float(h0));
    __nv_bfloat16 l1 = __float2bfloat16(r1 - __bfloat162float(h1));
    __nv_bfloat16 l2 = __float2bfloat16(r2 - __bfloat162float(h2));
    __nv_bfloat16 l3 = __float2bfloat16(r3 - __bfloat162float(h3));
    size_t idx = (size_t)m * DIM + c;
    __nv_bfloat162 ph0; ph0.x = h0; ph0.y = h1;
    __nv_bfloat162 ph1; ph1.x = h2; ph1.y = h3;
    __nv_bfloat162 pl0; pl0.x = l0; pl0.y = l1;
    __nv_bfloat162 pl1; pl1.x = l2; pl1.y = l3;
    ((__nv_bfloat162*)(fhi + idx))[0] = ph0;
    ((__nv_bfloat162*)(fhi + idx))[1] = ph1;
    ((__nv_bfloat162*)(flo + idx))[0] = pl0;
    ((__nv_bfloat162*)(flo + idx))[1] = pl1;
}

// ---------------- launch ----------------
extern "C" void kernel_launch(void* const* d_in, const int* in_sizes, int n_in,
                              void* d_out, int out_size) {
    const float* x    = (const float*)d_in[0];
    const float* Wq   = (const float*)d_in[1];
    const float* bq   = (const float*)d_in[2];
    const float* Wk   = (const float*)d_in[3];
    const float* bk   = (const float*)d_in[4];
    const float* Wv   = (const float*)d_in[5];
    const float* bv   = (const float*)d_in[6];
    const float* Wa   = (const float*)d_in[7];
    const float* ba   = (const float*)d_in[8];
    const float* Wb   = (const float*)d_in[9];
    const float* bb   = (const float*)d_in[10];
    const float* cwq  = (const float*)d_in[11];
    const float* cbq  = (const float*)d_in[12];
    const float* cwk  = (const float*)d_in[13];
    const float* cbk  = (const float*)d_in[14];
    const float* cwv  = (const float*)d_in[15];
    const float* cbv  = (const float*)d_in[16];
    const float* norm_w = (const float*)d_in[17];
    const float* Wg   = (const float*)d_in[18];
    const float* bg   = (const float*)d_in[19];
    const float* Wo   = (const float*)d_in[20];
    const float* bo   = (const float*)d_in[21];
    float* out = (float*)d_out;

    float *qlin, *klin, *vlin, *qn, *kn, *vn, *gate, *gdn, *al, *be;
    __nv_bfloat16 *xhi, *xlo, *fhi, *flo, *whi, *wlo;
    cudaGetSymbolAddress((void**)&qlin, g_qlin);
    cudaGetSymbolAddress((void**)&klin, g_klin);
    cudaGetSymbolAddress((void**)&vlin, g_vlin);
    cudaGetSymbolAddress((void**)&qn,   g_q);
    cudaGetSymbolAddress((void**)&kn,   g_k);
    cudaGetSymbolAddress((void**)&vn,   g_v);
    cudaGetSymbolAddress((void**)&gate, g_gate);
    cudaGetSymbolAddress((void**)&gdn,  g_gdn);
    cudaGetSymbolAddress((void**)&al,   g_alpha);
    cudaGetSymbolAddress((void**)&be,   g_beta);
    cudaGetSymbolAddress((void**)&xhi,  g_xhi);
    cudaGetSymbolAddress((void**)&xlo,  g_xlo);
    cudaGetSymbolAddress((void**)&fhi,  g_fhi);
    cudaGetSymbolAddress((void**)&flo,  g_flo);
    cudaGetSymbolAddress((void**)&whi,  g_whi);
    cudaGetSymbolAddress((void**)&wlo,  g_wlo);

    const int GEMM_SMEM = 2 * 4 * TILEB;  // 81920
    cudaFuncSetAttribute(gemm_mma<0>, cudaFuncAttributeMaxDynamicSharedMemorySize, GEMM_SMEM);
    cudaFuncSetAttribute(gemm_mma<1>, cudaFuncAttributeMaxDynamicSharedMemorySize, GEMM_SMEM);

    convert_split_kernel<<<MTOT*DIM/4/256, 256>>>(x, xhi, xlo, MTOT*DIM/4);
    const float* Ws[5] = {Wq, Wk, Wv, Wg, Wo};
    for (int w = 0; w < 5; w++)
        convert_split_kernel<<<DIM*DIM/4/256, 256>>>(
            Ws[w], whi + (size_t)w*DIM*DIM, wlo + (size_t)w*DIM*DIM, DIM*DIM/4);

    dim3 gg(MTOT/128, DIM/128);
    gemm_mma<0><<<gg, 256, GEMM_SMEM>>>(xhi, xlo, whi + 0*DIM*DIM, wlo + 0*DIM*DIM, bq, qlin);
    gemm_mma<0><<<gg, 256, GEMM_SMEM>>>(xhi, xlo, whi + 1*DIM*DIM, wlo + 1*DIM*DIM, bk, klin);
    gemm_mma<0><<<gg, 256, GEMM_SMEM>>>(xhi, xlo, whi + 2*DIM*DIM, wlo + 2*DIM*DIM, bv, vlin);
    gemm_mma<1><<<gg, 256, GEMM_SMEM>>>(xhi, xlo, whi + 3*DIM*DIM, wlo + 3*DIM*DIM, bg, gate);
    ab_kernel<<<MTOT / 8, 256>>>(x, Wa, ba, Wb, bb, al, be);

    conv_silu_kernel<<<MTOT, 128>>>(qlin, cwq, cbq, qn, 1);
    conv_silu_kernel<<<MTOT, 128>>>(klin, cwk, cbk, kn, 1);
    conv_silu_kernel<<<MTOT, 128>>>(vlin, cwv, cbv, vn, 0);

    scan_kernel<<<256, 128>>>(qn, kn, vn, al, be, gdn);

    norm_gate_kernel<<<MTOT, 128>>>(gdn, norm_w, gate, fhi, flo);
    gemm_mma<0><<<gg, 256, GEMM_SMEM>>>(fhi, flo, whi + 4*DIM*DIM, wlo + 4*DIM*DIM, bo, out);
}

// round 15
// speedup vs baseline: 1.4186x; 1.0073x over previous
#include <cuda_runtime.h>
#include <cuda_bf16.h>
#include <math.h>

#define BATCH 8
#define SLEN  2048
#define DIM   512
#define MTOT  (BATCH*SLEN)

// ---------------- scratch ----------------
__device__ float g_qlin[MTOT*DIM];
__device__ float g_klin[MTOT*DIM];
__device__ float g_vlin[MTOT*DIM];
__device__ float g_q[MTOT*DIM];
__device__ float g_k[MTOT*DIM];
__device__ float g_v[MTOT*DIM];
__device__ float g_gate[MTOT*DIM];
__device__ float g_gdn[MTOT*DIM];
__device__ float g_alpha[MTOT];
__device__ float g_beta[MTOT];
__device__ __align__(16) __nv_bfloat16 g_xhi[MTOT*DIM];
__device__ __align__(16) __nv_bfloat16 g_xlo[MTOT*DIM];
__device__ __align__(16) __nv_bfloat16 g_fhi[MTOT*DIM];
__device__ __align__(16) __nv_bfloat16 g_flo[MTOT*DIM];
__device__ __align__(16) __nv_bfloat16 g_whi[5*DIM*DIM];
__device__ __align__(16) __nv_bfloat16 g_wlo[5*DIM*DIM];

// ---------------- helpers ----------------
__device__ __forceinline__ unsigned long long fma2_(unsigned long long a,
                                                    unsigned long long b,
                                                    unsigned long long c) {
    unsigned long long d;
    asm("fma.rn.f32x2 %0, %1, %2, %3;" : "=l"(d) : "l"(a), "l"(b), "l"(c));
    return d;
}
__device__ __forceinline__ unsigned long long mul2_(unsigned long long a,
                                                    unsigned long long b) {
    unsigned long long d;
    asm("mul.rn.f32x2 %0, %1, %2;" : "=l"(d) : "l"(a), "l"(b));
    return d;
}
__device__ __forceinline__ unsigned long long pk2_(float lo, float hi) {
    unsigned long long r;
    asm("mov.b64 %0, {%1, %2};" : "=l"(r)
        : "r"(__float_as_uint(lo)), "r"(__float_as_uint(hi)));
    return r;
}
__device__ __forceinline__ float hadd2_(unsigned long long a) {
    unsigned int l, h;
    asm("mov.b64 {%0, %1}, %2;" : "=r"(l), "=r"(h) : "l"(a));
    return __uint_as_float(l) + __uint_as_float(h);
}
__device__ __forceinline__ float wredsum_(float v) {
    #pragma unroll
    for (int off = 16; off; off >>= 1) v += __shfl_xor_sync(0xffffffffu, v, off);
    return v;
}
__device__ __forceinline__ float silu_(float x) { return x / (1.0f + __expf(-x)); }
__device__ __forceinline__ void cpasync16_(unsigned int dst, const void* src) {
    asm volatile("cp.async.cg.shared.global [%0], [%1], 16;"
                 :: "r"(dst), "l"(src) : "memory");
}
__device__ __forceinline__ unsigned int smem_u32_(const void* p) {
    unsigned int a;
    asm("{ .reg .u64 t; cvta.to.shared.u64 t, %1; cvt.u32.u64 %0, t; }"
        : "=r"(a) : "l"(p));
    return a;
}
__device__ __forceinline__ void ldsm4_(unsigned& r0, unsigned& r1, unsigned& r2,
                                       unsigned& r3, unsigned addr) {
    asm volatile("ldmatrix.sync.aligned.m8n8.x4.shared.b16 {%0,%1,%2,%3}, [%4];"
                 : "=r"(r0), "=r"(r1), "=r"(r2), "=r"(r3) : "r"(addr));
}
__device__ __forceinline__ void mma16816_(float* d, const unsigned* a,
                                          const unsigned* b) {
    asm volatile(
        "mma.sync.aligned.m16n8k16.row.col.f32.bf16.bf16.f32 "
        "{%0,%1,%2,%3}, {%4,%5,%6,%7}, {%8,%9}, {%0,%1,%2,%3};"
        : "+f"(d[0]), "+f"(d[1]), "+f"(d[2]), "+f"(d[3])
        : "r"(a[0]), "r"(a[1]), "r"(a[2]), "r"(a[3]), "r"(b[0]), "r"(b[1]));
}

// ---------------- fp32 -> bf16 hi/lo split ----------------
__global__ void __launch_bounds__(256) convert_split_kernel(
    const float* __restrict__ src, __nv_bfloat16* __restrict__ hi,
    __nv_bfloat16* __restrict__ lo, int n4)
{
    int i = blockIdx.x * 256 + threadIdx.x;
    if (i >= n4) return;
    float4 v = ((const float4*)src)[i];
    __nv_bfloat16 h0 = __float2bfloat16(v.x);
    __nv_bfloat16 h1 = __float2bfloat16(v.y);
    __nv_bfloat16 h2 = __float2bfloat16(v.z);
    __nv_bfloat16 h3 = __float2bfloat16(v.w);
    __nv_bfloat16 l0 = __float2bfloat16(v.x - __bfloat162float(h0));
    __nv_bfloat16 l1 = __float2bfloat16(v.y - __bfloat162float(h1));
    __nv_bfloat16 l2 = __float2bfloat16(v.z - __bfloat162float(h2));
    __nv_bfloat16 l3 = __float2bfloat16(v.w - __bfloat162float(h3));
    __nv_bfloat162 ph0; ph0.x = h0; ph0.y = h1;
    __nv_bfloat162 ph1; ph1.x = h2; ph1.y = h3;
    __nv_bfloat162 pl0; pl0.x = l0; pl0.y = l1;
    __nv_bfloat162 pl1; pl1.x = l2; pl1.y = l3;
    ((__nv_bfloat162*)hi)[2*i]   = ph0;
    ((__nv_bfloat162*)hi)[2*i+1] = ph1;
    ((__nv_bfloat162*)lo)[2*i]   = pl0;
    ((__nv_bfloat162*)lo)[2*i+1] = pl1;
}

// ---------------- mma.sync bf16-split GEMM: C = A @ W^T + bias (+SiLU) -------
// CTA 128x128, 256 threads (8 warps: 4 in M x 2 in N, warp tile 32x64).
// 2 CTAs/SM (regs<=128), single __syncthreads per K-chunk, B frags loaded
// per-p to bound live registers. 3 products: AhBh + AhBl + AlBh.
#define GROW 80           // bytes per smem row (32 bf16 + 8 pad)
#define TILEB (128*GROW)  // 10240 bytes per tile
template<int ACT>
__global__ void __launch_bounds__(256, 2) gemm_mma(
    const __nv_bfloat16* __restrict__ Ah, const __nv_bfloat16* __restrict__ Al,
    const __nv_bfloat16* __restrict__ Wh, const __nv_bfloat16* __restrict__ Wl,
    const float* __restrict__ bias, float* __restrict__ C)
{
    extern __shared__ char dsm[];      // 2 * 4 * TILEB = 81920 bytes
    const int tid  = threadIdx.x;
    const int wid  = tid >> 5;
    const int lane = tid & 31;
    const int wm = wid >> 1;           // 0..3
    const int wn = wid & 1;            // 0..1
    const int m0 = blockIdx.x * 128;
    const int n0 = blockIdx.y * 128;

    unsigned int sb = smem_u32_(dsm);
    const __nv_bfloat16* gsrc[4] = {Ah, Al, Wh, Wl};
    const int gbase[4] = {m0, m0, n0, n0};

    auto stage = [&](int kc, int buf) {
        unsigned int bb = sb + buf * (4 * TILEB);
        #pragma unroll
        for (int it = 0; it < 8; it++) {
            int i = tid + it * 256;
            int tile = i >> 9;
            int j = i & 511;
            int row = j >> 2, seg = j & 3;
            cpasync16_(bb + tile * TILEB + row * GROW + seg * 16,
                       gsrc[tile] + (size_t)(gbase[tile] + row) * DIM + kc * 32 + seg * 8);
        }
        asm volatile("cp.async.commit_group;" ::: "memory");
    };

    stage(0, 0);

    float acc[2][8][4];
    #pragma unroll
    for (int mt = 0; mt < 2; mt++)
        #pragma unroll
        for (int nt = 0; nt < 8; nt++)
            #pragma unroll
            for (int c = 0; c < 4; c++) acc[mt][nt][c] = 0.f;

    const int arow = wm * 32 + (lane & 15);
    const int acol = (lane >> 4) * 16;
    const int brow = wn * 64 + (lane & 7) + (((lane >> 4) & 1) << 3);
    const int bcol = ((lane >> 3) & 1) * 16;

    #pragma unroll 1
    for (int kc = 0; kc < 16; ++kc) {
        // copy(kc) complete; sync also guarantees all warps done reading the
        // buffer that stage(kc+1) will overwrite (read two iterations ago).
        asm volatile("cp.async.wait_group 0;" ::: "memory");
        __syncthreads();
        if (kc + 1 < 16) stage(kc + 1, (kc + 1) & 1);

        unsigned int bb = sb + (kc & 1) * (4 * TILEB);
        unsigned int tAh = bb, tAl = bb + TILEB, tWh = bb + 2*TILEB, tWl = bb + 3*TILEB;

        #pragma unroll
        for (int ks = 0; ks < 2; ks++) {
            unsigned ah[2][4], al[2][4];
            #pragma unroll
            for (int mt = 0; mt < 2; mt++) {
                unsigned aoff = (arow + mt * 16) * GROW + ks * 32 + acol;
                ldsm4_(ah[mt][0], ah[mt][1], ah[mt][2], ah[mt][3], tAh + aoff);
                ldsm4_(al[mt][0], al[mt][1], al[mt][2], al[mt][3], tAl + aoff);
            }
            #pragma unroll
            for (int p = 0; p < 4; p++) {
                unsigned bh4[4], bl4[4];
                unsigned boff = (brow + p * 16) * GROW + ks * 32 + bcol;
                ldsm4_(bh4[0], bh4[1], bh4[2], bh4[3], tWh + boff);
                ldsm4_(bl4[0], bl4[1], bl4[2], bl4[3], tWl + boff);
                #pragma unroll
                for (int mt = 0; mt < 2; mt++) {
                    #pragma unroll
                    for (int sub = 0; sub < 2; sub++) {
                        float* ac = acc[mt][p * 2 + sub];
                        mma16816_(ac, ah[mt], &bh4[sub * 2]);
                        mma16816_(ac, ah[mt], &bl4[sub * 2]);
                        mma16816_(ac, al[mt], &bh4[sub * 2]);
                    }
                }
            }
        }
    }

    const int g = lane >> 2;
    const int cc = (lane & 3) * 2;
    #pragma unroll
    for (int mt = 0; mt < 2; mt++) {
        #pragma unroll
        for (int nt = 0; nt < 8; nt++) {
            int col = n0 + wn * 64 + nt * 8 + cc;
            float2 bv = *(const float2*)(bias + col);
            int row0 = m0 + wm * 32 + mt * 16 + g;
            float c0 = acc[mt][nt][0] + bv.x;
            float c1 = acc[mt][nt][1] + bv.y;
            float c2 = acc[mt][nt][2] + bv.x;
            float c3 = acc[mt][nt][3] + bv.y;
            if (ACT == 1) { c0 = silu_(c0); c1 = silu_(c1); c2 = silu_(c2); c3 = silu_(c3); }
            *(float2*)(C + (size_t)row0 * DIM + col)       = make_float2(c0, c1);
            *(float2*)(C + (size_t)(row0 + 8) * DIM + col) = make_float2(c2, c3);
        }
    }
}

// ---------------- alpha/beta GEMV + sigmoid ----------------
__global__ void __launch_bounds__(256) ab_kernel(
    const float* __restrict__ x,
    const float* __restrict__ Wa, const float* __restrict__ ba,
    const float* __restrict__ Wb, const float* __restrict__ bb,
    float* __restrict__ alpha, float* __restrict__ beta)
{
    const int warp = threadIdx.x >> 5, lane = threadIdx.x & 31;
    const int m = blockIdx.x * 8 + warp;
    const float* xr = x + (size_t)m * DIM;
    float sa = 0.f, sb = 0.f;
    #pragma unroll
    for (int i = 0; i < 4; i++) {
        float4 xv = *(const float4*)(xr + i * 128 + (lane << 2));
        float4 wa = *(const float4*)(Wa + i * 128 + (lane << 2));
        float4 wb = *(const float4*)(Wb + i * 128 + (lane << 2));
        sa += xv.x*wa.x + xv.y*wa.y + xv.z*wa.z + xv.w*wa.w;
        sb += xv.x*wb.x + xv.y*wb.y + xv.z*wb.z + xv.w*wb.w;
    }
    sa = wredsum_(sa);
    sb = wredsum_(sb);
    if (lane == 0) {
        alpha[m] = 1.0f / (1.0f + __expf(-(sa + ba[0])));
        beta[m]  = 1.0f / (1.0f + __expf(-(sb + bb[0])));
    }
}

// ---------------- depthwise causal conv(4) + SiLU (+ optional L2 norm) -------
__global__ void __launch_bounds__(128) conv_silu_kernel(
    const float* __restrict__ lin, const float* __restrict__ cw,
    const float* __restrict__ cb, float* __restrict__ outp, int do_l2)
{
    __shared__ float red[4];
    const int m = blockIdx.x;
    const int s = m & (SLEN - 1);
    const int c = threadIdx.x << 2;
    const int lane = threadIdx.x & 31;
    const int warp = threadIdx.x >> 5;

    float w[4][4];
    #pragma unroll
    for (int ch = 0; ch < 4; ++ch) {
        float4 wv = *(const float4*)(cw + (size_t)(c + ch) * 4);
        w[ch][0] = wv.x; w[ch][1] = wv.y; w[ch][2] = wv.z; w[ch][3] = wv.w;
    }
    float4 bv = *(const float4*)(cb + c);
    float y0 = bv.x, y1 = bv.y, y2 = bv.z, y3 = bv.w;
    #pragma unroll
    for (int tau = 0; tau < 4; ++tau) {
        int sp = s - 3 + tau;
        if (sp >= 0) {
            float4 xv = *(const float4*)(lin + (size_t)(m - 3 + tau) * DIM + c);
            y0 += w[0][tau] * xv.x;
            y1 += w[1][tau] * xv.y;
            y2 += w[2][tau] * xv.z;
            y3 += w[3][tau] * xv.w;
        }
    }
    y0 = silu_(y0); y1 = silu_(y1); y2 = silu_(y2); y3 = silu_(y3);
    float sc = 1.0f;
    if (do_l2) {
        float ss = wredsum_(y0*y0 + y1*y1 + y2*y2 + y3*y3);
        if (lane == 0) red[warp] = ss;
        __syncthreads();
        float tot = red[0] + red[1] + red[2] + red[3];
        sc = 1.0f / fmaxf(sqrtf(tot), 1e-12f);
    }
    *(float4*)(outp + (size_t)m * DIM + c) = make_float4(y0*sc, y1*sc, y2*sc, y3*sc);
}

// ---------------- gated delta-rule scan (2 steps fused) ----------------------
// 512 CTAs x 64 threads (2 warps x 4 rows = 8 rows/CTA), 3-4 CTAs/SM for
// balance + independent barrier groups. 3-buffer cp.async pipeline.
__global__ void __launch_bounds__(64, 6) scan_kernel(
    const float* __restrict__ qn, const float* __restrict__ kn,
    const float* __restrict__ vn, const float* __restrict__ alpha,
    const float* __restrict__ beta, float* __restrict__ outp)
{
    const int tid  = threadIdx.x;
    const int warp = tid >> 5;           // 0..1
    const int lane = tid & 31;
    const int cta  = blockIdx.x;         // 0..511
    const int b    = cta >> 6;           // 64 CTAs per batch
    const int i0   = ((cta & 63) << 3) + (warp << 2);   // 8 rows/CTA

    const float* kp = kn + (size_t)b * SLEN * DIM;
    const float* qp = qn + (size_t)b * SLEN * DIM;
    const float* vp = vn + (size_t)b * SLEN * DIM + i0;
    const float* ap = alpha + (size_t)b * SLEN;
    const float* bp = beta  + (size_t)b * SLEN;
    float* op = outp + (size_t)b * SLEN * DIM + i0;

    // smem: 3 buffers x [k0|q0|k1|q1] x 512 floats = 24 KB
    __shared__ __align__(16) float sbuf[3][2048];
    unsigned int sbase = smem_u32_(sbuf);
    // staging: 64 threads, section = tid>>4 (k0,q0,k1,q1), 8 float4s each
    const int sec = tid >> 4;
    const int t16 = tid & 15;
    const float* gsecN = ((sec & 1) ? qp : kp) + (sec >> 1) * DIM + t16 * 4;
    const unsigned int soff = sec * 2048 + t16 * 16;

    #pragma unroll
    for (int m = 0; m < 8; m++)
        cpasync16_(sbase + soff + m * 256, gsecN + m * 64);
    asm volatile("cp.async.commit_group;" ::: "memory");
    #pragma unroll
    for (int m = 0; m < 8; m++)
        cpasync16_(sbase + 8192 + soff + m * 256, gsecN + 2 * DIM + m * 64);
    asm volatile("cp.async.commit_group;" ::: "memory");

    unsigned long long z[4][8];
    #pragma unroll
    for (int r = 0; r < 4; r++)
        #pragma unroll
        for (int e = 0; e < 8; e++) z[r][e] = 0ULL;

    float A = 1.0f;
    const unsigned FULL = 0xffffffffu;
    int cur = 0, nxt = 2;

    const bool isout = (lane & 3) == 2;
    const int ostep = (lane >> 2) & 1;
    const int orow = ((lane >> 4) & 1) + (((lane >> 3) & 1) << 1);

    #pragma unroll 1
    for (int i = 0; i < SLEN / 2; ++i) {
        asm volatile("cp.async.wait_group 1;" ::: "memory");
        __syncthreads();
        if (i + 2 < SLEN / 2) {
            const float* gs2 = gsecN + (size_t)(2 * i + 4) * DIM;
            #pragma unroll
            for (int m = 0; m < 8; m++)
                cpasync16_(sbase + nxt * 8192 + soff + m * 256, gs2 + m * 64);
        }
        asm volatile("cp.async.commit_group;" ::: "memory");

        unsigned long long kc0[8], qc0[8], kc1[8], qc1[8];
        {
            const float4* f0 = (const float4*)&sbuf[cur][0];
            const float4* f1 = (const float4*)&sbuf[cur][512];
            const float4* f2 = (const float4*)&sbuf[cur][1024];
            const float4* f3 = (const float4*)&sbuf[cur][1536];
            #pragma unroll
            for (int m = 0; m < 4; m++) {
                float4 u;
                u = f0[m * 32 + lane]; kc0[2*m] = pk2_(u.x,u.y); kc0[2*m+1] = pk2_(u.z,u.w);
                u = f1[m * 32 + lane]; qc0[2*m] = pk2_(u.x,u.y); qc0[2*m+1] = pk2_(u.z,u.w);
                u = f2[m * 32 + lane]; kc1[2*m] = pk2_(u.x,u.y); kc1[2*m+1] = pk2_(u.z,u.w);
                u = f3[m * 32 + lane]; qc1[2*m] = pk2_(u.x,u.y); qc1[2*m+1] = pk2_(u.z,u.w);
            }
        }
        float4 v0 = *(const float4*)(vp + (size_t)(2 * i) * DIM);
        float4 v1 = *(const float4*)(vp + (size_t)(2 * i + 1) * DIM);
        float2 a2 = *(const float2*)(ap + 2 * i);
        float2 b2 = *(const float2*)(bp + 2 * i);

        unsigned long long zka[4] = {0,0,0,0}, zqa[4] = {0,0,0,0};
        unsigned long long zkb[4] = {0,0,0,0}, zqb[4] = {0,0,0,0};
        unsigned long long c00a = 0, c01a = 0, cka = 0, c11a = 0;
        #pragma unroll
        for (int e = 0; e < 8; e++) {
            #pragma unroll
            for (int r = 0; r < 4; r++) {
                zka[r] = fma2_(z[r][e], kc0[e], zka[r]);
                zqa[r] = fma2_(z[r][e], qc0[e], zqa[r]);
                zkb[r] = fma2_(z[r][e], kc1[e], zkb[r]);
                zqb[r] = fma2_(z[r][e], qc1[e], zqb[r]);
            }
            c00a = fma2_(kc0[e], qc0[e], c00a);
            c01a = fma2_(kc0[e], qc1[e], c01a);
            cka  = fma2_(kc0[e], kc1[e], cka);
            c11a = fma2_(kc1[e], qc1[e], c11a);
        }
        float d[16];
        d[0]=hadd2_(zka[0]); d[1]=hadd2_(zka[1]); d[2]=hadd2_(zka[2]); d[3]=hadd2_(zka[3]);
        d[4]=hadd2_(zkb[0]); d[5]=hadd2_(zkb[1]); d[6]=hadd2_(zkb[2]); d[7]=hadd2_(zkb[3]);
        d[8]=hadd2_(zqa[0]); d[9]=hadd2_(zqa[1]); d[10]=hadd2_(zqa[2]); d[11]=hadd2_(zqa[3]);
        d[12]=hadd2_(zqb[0]); d[13]=hadd2_(zqb[1]); d[14]=hadd2_(zqb[2]); d[15]=hadd2_(zqb[3]);
        float f;
        {
            float x[16];
            #pragma unroll
            for (int j = 0; j < 16; j++) x[j] = d[j] + __shfl_xor_sync(FULL, d[j], 16);
            bool s4 = (lane & 16) != 0;
            float w8[8];
            #pragma unroll
            for (int j = 0; j < 8; j++) w8[j] = s4 ? x[2*j+1] : x[2*j];
            float y8[8];
            #pragma unroll
            for (int j = 0; j < 8; j++) y8[j] = w8[j] + __shfl_xor_sync(FULL, w8[j], 8);
            bool s3 = (lane & 8) != 0;
            float u4[4];
            #pragma unroll
            for (int j = 0; j < 4; j++) u4[j] = s3 ? y8[2*j+1] : y8[2*j];
            float t4[4];
            #pragma unroll
            for (int j = 0; j < 4; j++) t4[j] = u4[j] + __shfl_xor_sync(FULL, u4[j], 4);
            bool s2 = (lane & 4) != 0;
            float sv[2];
            sv[0] = s2 ? t4[1] : t4[0];
            sv[1] = s2 ? t4[3] : t4[2];
            float rv[2];
            rv[0] = sv[0] + __shfl_xor_sync(FULL, sv[0], 2);
            rv[1] = sv[1] + __shfl_xor_sync(FULL, sv[1], 2);
            float qv = (lane & 2) ? rv[1] : rv[0];
            f = qv + __shfl_xor_sync(FULL, qv, 1);
        }
        float c00, c01, ck, c11;
        {
            float e0 = hadd2_(c00a), e1 = hadd2_(c01a), e2 = hadd2_(cka), e3 = hadd2_(c11a);
            float x0 = e0 + __shfl_xor_sync(FULL, e0, 16);
            float x1 = e1 + __shfl_xor_sync(FULL, e1, 16);
            float x2 = e2 + __shfl_xor_sync(FULL, e2, 16);
            float x3 = e3 + __shfl_xor_sync(FULL, e3, 16);
            bool s4 = (lane & 16) != 0;
            float g0 = s4 ? x1 : x0;
            float g1 = s4 ? x3 : x2;
            float y0 = g0 + __shfl_xor_sync(FULL, g0, 8);
            float y1 = g1 + __shfl_xor_sync(FULL, g1, 8);
            float h = (lane & 8) ? y1 : y0;
            h += __shfl_xor_sync(FULL, h, 4);
            h += __shfl_xor_sync(FULL, h, 2);
            h += __shfl_xor_sync(FULL, h, 1);
            c00 = __shfl_sync(FULL, h, 0);
            c01 = __shfl_sync(FULL, h, 16);
            ck  = __shfl_sync(FULL, h, 8);
            c11 = __shfl_sync(FULL, h, 24);
        }
        float zk0r[4], zk1r[4];
        zk0r[0] = __shfl_sync(FULL, f, 0);
        zk0r[1] = __shfl_sync(FULL, f, 16);
        zk0r[2] = __shfl_sync(FULL, f, 8);
        zk0r[3] = __shfl_sync(FULL, f, 24);
        zk1r[0] = __shfl_sync(FULL, f, 4);
        zk1r[1] = __shfl_sync(FULL, f, 20);
        zk1r[2] = __shfl_sync(FULL, f, 12);
        zk1r[3] = __shfl_sync(FULL, f, 28);

        float A1 = A * a2.x;
        float rA1 = 1.0f / A1;
        float ab0 = a2.x * b2.x;
        float vv0[4] = {v0.x, v0.y, v0.z, v0.w};
        float vv1[4] = {v1.x, v1.y, v1.z, v1.w};
        float w0v[4], w1v[4];
        #pragma unroll
        for (int r = 0; r < 4; r++)
            w0v[r] = (b2.x * vv0[r] - ab0 * (A * zk0r[r])) * rA1;
        float A2f = A1 * a2.y;
        float rA2 = 1.0f / A2f;
        float ab1 = a2.y * b2.y;
        #pragma unroll
        for (int r = 0; r < 4; r++) {
            float sk1 = A1 * (zk1r[r] + w0v[r] * ck);
            w1v[r] = (b2.y * vv1[r] - ab1 * sk1) * rA2;
        }

        #pragma unroll
        for (int r = 0; r < 4; r++) {
            unsigned long long W0 = pk2_(w0v[r], w0v[r]);
            unsigned long long W1 = pk2_(w1v[r], w1v[r]);
            #pragma unroll
            for (int e = 0; e < 8; e++)
                z[r][e] = fma2_(W1, kc1[e], fma2_(W0, kc0[e], z[r][e]));
        }

        if (isout) {
            float o;
            if (ostep == 0) o = A1 * (f + w0v[orow] * c00);
            else            o = A2f * (f + w0v[orow] * c01 + w1v[orow] * c11);
            op[(size_t)(2 * i + ostep) * DIM + orow] = o;
        }

        A = A2f;
        if ((i & 7) == 7) {
            unsigned long long AA = pk2_(A, A);
            #pragma unroll
            for (int r = 0; r < 4; r++)
                #pragma unroll
                for (int e = 0; e < 8; e++) z[r][e] = mul2_(z[r][e], AA);
            A = 1.0f;
        }

        cur = (cur == 2) ? 0 : cur + 1;
        nxt = (nxt == 2) ? 0 : nxt + 1;
    }
}

// ---------------- zero-centered RMSNorm * gate -> bf16 hi/lo split -----------
__global__ void __launch_bounds__(128) norm_gate_kernel(
    const float* __restrict__ gdn, const float* __restrict__ norm_w,
    const float* __restrict__ gate,
    __nv_bfloat16* __restrict__ fhi, __nv_bfloat16* __restrict__ flo)
{
    __shared__ float rs[4], rq[4];
    const int m = blockIdx.x;
    const int c = threadIdx.x << 2;
    const int lane = threadIdx.x & 31;
    const int warp = threadIdx.x >> 5;

    float4 xv = *(const float4*)(gdn + (size_t)m * DIM + c);
    float s = wredsum_(xv.x + xv.y + xv.z + xv.w);
    float q = wredsum_(xv.x*xv.x + xv.y*xv.y + xv.z*xv.z + xv.w*xv.w);
    if (lane == 0) { rs[warp] = s; rq[warp] = q; }
    __syncthreads();
    float sum = rs[0] + rs[1] + rs[2] + rs[3];
    float sq  = rq[0] + rq[1] + rq[2] + rq[3];
    float mean = sum * (1.0f / DIM);
    float var  = sq * (1.0f / DIM) - mean * mean;
    float inv  = rsqrtf(var + 1e-5f);

    float4 wv = *(const float4*)(norm_w + c);
    float4 gv = *(const float4*)(gate + (size_t)m * DIM + c);
    float r0 = (xv.x - mean) * inv * wv.x * gv.x;
    float r1 = (xv.y - mean) * inv * wv.y * gv.y;
    float r2 = (xv.z - mean) * inv * wv.z * gv.z;
    float r3 = (xv.w - mean) * inv * wv.w * gv.w;

    __nv_bfloat16 h0 = __float2bfloat16(r0), h1 = __float2bfloat16(r1);
    __nv_bfloat16 h2 = __float2bfloat16(r2), h3 = __float2bfloat16(r3);
    __nv_bfloat16 l0 = __float2bfloat16(r0 - __bfloat162float(h0));
    __nv_bfloat16 l1 = __float2bfloat16(r1 - __bfloat162float(h1));
    __nv_bfloat16 l2 = __float2bfloat16(r2 - __bfloat162float(h2));
    __nv_bfloat16 l3 = __float2bfloat16(r3 - __bfloat162float(h3));
    size_t idx = (size_t)m * DIM + c;
    __nv_bfloat162 ph0; ph0.x = h0; ph0.y = h1;
    __nv_bfloat162 ph1; ph1.x = h2; ph1.y = h3;
    __nv_bfloat162 pl0; pl0.x = l0; pl0.y = l1;
    __nv_bfloat162 pl1; pl1.x = l2; pl1.y = l3;
    ((__nv_bfloat162*)(fhi + idx))[0] = ph0;
    ((__nv_bfloat162*)(fhi + idx))[1] = ph1;
    ((__nv_bfloat162*)(flo + idx))[0] = pl0;
    ((__nv_bfloat162*)(flo + idx))[1] = pl1;
}

// ---------------- launch ----------------
extern "C" void kernel_launch(void* const* d_in, const int* in_sizes, int n_in,
                              void* d_out, int out_size) {
    const float* x    = (const float*)d_in[0];
    const float* Wq   = (const float*)d_in[1];
    const float* bq   = (const float*)d_in[2];
    const float* Wk   = (const float*)d_in[3];
    const float* bk   = (const float*)d_in[4];
    const float* Wv   = (const float*)d_in[5];
    const float* bv   = (const float*)d_in[6];
    const float* Wa   = (const float*)d_in[7];
    const float* ba   = (const float*)d_in[8];
    const float* Wb   = (const float*)d_in[9];
    const float* bb   = (const float*)d_in[10];
    const float* cwq  = (const float*)d_in[11];
    const float* cbq  = (const float*)d_in[12];
    const float* cwk  = (const float*)d_in[13];
    const float* cbk  = (const float*)d_in[14];
    const float* cwv  = (const float*)d_in[15];
    const float* cbv  = (const float*)d_in[16];
    const float* norm_w = (const float*)d_in[17];
    const float* Wg   = (const float*)d_in[18];
    const float* bg   = (const float*)d_in[19];
    const float* Wo   = (const float*)d_in[20];
    const float* bo   = (const float*)d_in[21];
    float* out = (float*)d_out;

    float *qlin, *klin, *vlin, *qn, *kn, *vn, *gate, *gdn, *al, *be;
    __nv_bfloat16 *xhi, *xlo, *fhi, *flo, *whi, *wlo;
    cudaGetSymbolAddress((void**)&qlin, g_qlin);
    cudaGetSymbolAddress((void**)&klin, g_klin);
    cudaGetSymbolAddress((void**)&vlin, g_vlin);
    cudaGetSymbolAddress((void**)&qn,   g_q);
    cudaGetSymbolAddress((void**)&kn,   g_k);
    cudaGetSymbolAddress((void**)&vn,   g_v);
    cudaGetSymbolAddress((void**)&gate, g_gate);
    cudaGetSymbolAddress((void**)&gdn,  g_gdn);
    cudaGetSymbolAddress((void**)&al,   g_alpha);
    cudaGetSymbolAddress((void**)&be,   g_beta);
    cudaGetSymbolAddress((void**)&xhi,  g_xhi);
    cudaGetSymbolAddress((void**)&xlo,  g_xlo);
    cudaGetSymbolAddress((void**)&fhi,  g_fhi);
    cudaGetSymbolAddress((void**)&flo,  g_flo);
    cudaGetSymbolAddress((void**)&whi,  g_whi);
    cudaGetSymbolAddress((void**)&wlo,  g_wlo);

    const int GEMM_SMEM = 2 * 4 * TILEB;  // 81920
    cudaFuncSetAttribute(gemm_mma<0>, cudaFuncAttributeMaxDynamicSharedMemorySize, GEMM_SMEM);
    cudaFuncSetAttribute(gemm_mma<1>, cudaFuncAttributeMaxDynamicSharedMemorySize, GEMM_SMEM);

    convert_split_kernel<<<MTOT*DIM/4/256, 256>>>(x, xhi, xlo, MTOT*DIM/4);
    const float* Ws[5] = {Wq, Wk, Wv, Wg, Wo};
    for (int w = 0; w < 5; w++)
        convert_split_kernel<<<DIM*DIM/4/256, 256>>>(
            Ws[w], whi + (size_t)w*DIM*DIM, wlo + (size_t)w*DIM*DIM, DIM*DIM/4);

    dim3 gg(MTOT/128, DIM/128);
    gemm_mma<0><<<gg, 256, GEMM_SMEM>>>(xhi, xlo, whi + 0*DIM*DIM, wlo + 0*DIM*DIM, bq, qlin);
    gemm_mma<0><<<gg, 256, GEMM_SMEM>>>(xhi, xlo, whi + 1*DIM*DIM, wlo + 1*DIM*DIM, bk, klin);
    gemm_mma<0><<<gg, 256, GEMM_SMEM>>>(xhi, xlo, whi + 2*DIM*DIM, wlo + 2*DIM*DIM, bv, vlin);
    gemm_mma<1><<<gg, 256, GEMM_SMEM>>>(xhi, xlo, whi + 3*DIM*DIM, wlo + 3*DIM*DIM, bg, gate);
    ab_kernel<<<MTOT / 8, 256>>>(x, Wa, ba, Wb, bb, al, be);

    conv_silu_kernel<<<MTOT, 128>>>(qlin, cwq, cbq, qn, 1);
    conv_silu_kernel<<<MTOT, 128>>>(klin, cwk, cbk, kn, 1);
    conv_silu_kernel<<<MTOT, 128>>>(vlin, cwv, cbv, vn, 0);

    scan_kernel<<<512, 64>>>(qn, kn, vn, al, be, gdn);

    norm_gate_kernel<<<MTOT, 128>>>(gdn, norm_w, gate, fhi, flo);
    gemm_mma<0><<<gg, 256, GEMM_SMEM>>>(fhi, flo, whi + 4*DIM*DIM, wlo + 4*DIM*DIM, bo, out);
}

// round 16
// speedup vs baseline: 1.4223x; 1.0026x over previous
#include <cuda_runtime.h>
#include <cuda_bf16.h>
#include <math.h>

#define BATCH 8
#define SLEN  2048
#define DIM   512
#define MTOT  (BATCH*SLEN)
#define NQKVG 2048

// ---------------- scratch ----------------
__device__ float g_qkvg[(size_t)MTOT*NQKVG];   // q|k|v|gate stacked columns
__device__ float g_q[MTOT*DIM];
__device__ float g_k[MTOT*DIM];
__device__ float g_v[MTOT*DIM];
__device__ float g_gdn[MTOT*DIM];
__device__ float g_alpha[MTOT];
__device__ float g_beta[MTOT];
__device__ float g_bias4[NQKVG];
__device__ __align__(16) __nv_bfloat16 g_xhi[MTOT*DIM];
__device__ __align__(16) __nv_bfloat16 g_xlo[MTOT*DIM];
__device__ __align__(16) __nv_bfloat16 g_fhi[MTOT*DIM];
__device__ __align__(16) __nv_bfloat16 g_flo[MTOT*DIM];
__device__ __align__(16) __nv_bfloat16 g_whi[5*DIM*DIM];
__device__ __align__(16) __nv_bfloat16 g_wlo[5*DIM*DIM];

// ---------------- helpers ----------------
__device__ __forceinline__ unsigned long long fma2_(unsigned long long a,
                                                    unsigned long long b,
                                                    unsigned long long c) {
    unsigned long long d;
    asm("fma.rn.f32x2 %0, %1, %2, %3;" : "=l"(d) : "l"(a), "l"(b), "l"(c));
    return d;
}
__device__ __forceinline__ unsigned long long mul2_(unsigned long long a,
                                                    unsigned long long b) {
    unsigned long long d;
    asm("mul.rn.f32x2 %0, %1, %2;" : "=l"(d) : "l"(a), "l"(b));
    return d;
}
__device__ __forceinline__ unsigned long long pk2_(float lo, float hi) {
    unsigned long long r;
    asm("mov.b64 %0, {%1, %2};" : "=l"(r)
        : "r"(__float_as_uint(lo)), "r"(__float_as_uint(hi)));
    return r;
}
__device__ __forceinline__ float hadd2_(unsigned long long a) {
    unsigned int l, h;
    asm("mov.b64 {%0, %1}, %2;" : "=r"(l), "=r"(h) : "l"(a));
    return __uint_as_float(l) + __uint_as_float(h);
}
__device__ __forceinline__ float wredsum_(float v) {
    #pragma unroll
    for (int off = 16; off; off >>= 1) v += __shfl_xor_sync(0xffffffffu, v, off);
    return v;
}
__device__ __forceinline__ float silu_(float x) { return x / (1.0f + __expf(-x)); }
__device__ __forceinline__ void cpasync16_(unsigned int dst, const void* src) {
    asm volatile("cp.async.cg.shared.global [%0], [%1], 16;"
                 :: "r"(dst), "l"(src) : "memory");
}
__device__ __forceinline__ unsigned int smem_u32_(const void* p) {
    unsigned int a;
    asm("{ .reg .u64 t; cvta.to.shared.u64 t, %1; cvt.u32.u64 %0, t; }"
        : "=r"(a) : "l"(p));
    return a;
}
__device__ __forceinline__ void ldsm4_(unsigned& r0, unsigned& r1, unsigned& r2,
                                       unsigned& r3, unsigned addr) {
    asm volatile("ldmatrix.sync.aligned.m8n8.x4.shared.b16 {%0,%1,%2,%3}, [%4];"
                 : "=r"(r0), "=r"(r1), "=r"(r2), "=r"(r3) : "r"(addr));
}
__device__ __forceinline__ void mma16816_(float* d, const unsigned* a,
                                          const unsigned* b) {
    asm volatile(
        "mma.sync.aligned.m16n8k16.row.col.f32.bf16.bf16.f32 "
        "{%0,%1,%2,%3}, {%4,%5,%6,%7}, {%8,%9}, {%0,%1,%2,%3};"
        : "+f"(d[0]), "+f"(d[1]), "+f"(d[2]), "+f"(d[3])
        : "r"(a[0]), "r"(a[1]), "r"(a[2]), "r"(a[3]), "r"(b[0]), "r"(b[1]));
}

// ---------------- bias pack ----------------
__global__ void pack_bias_kernel(const float* bq, const float* bk,
                                 const float* bv, const float* bg,
                                 float* out) {
    int i = blockIdx.x * 256 + threadIdx.x;
    if (i >= NQKVG) return;
    const float* src = (i < 512) ? bq : (i < 1024) ? bk : (i < 1536) ? bv : bg;
    out[i] = src[i & 511];
}

// ---------------- fp32 -> bf16 hi/lo split ----------------
__global__ void __launch_bounds__(256) convert_split_kernel(
    const float* __restrict__ src, __nv_bfloat16* __restrict__ hi,
    __nv_bfloat16* __restrict__ lo, int n4)
{
    int i = blockIdx.x * 256 + threadIdx.x;
    if (i >= n4) return;
    float4 v = ((const float4*)src)[i];
    __nv_bfloat16 h0 = __float2bfloat16(v.x);
    __nv_bfloat16 h1 = __float2bfloat16(v.y);
    __nv_bfloat16 h2 = __float2bfloat16(v.z);
    __nv_bfloat16 h3 = __float2bfloat16(v.w);
    __nv_bfloat16 l0 = __float2bfloat16(v.x - __bfloat162float(h0));
    __nv_bfloat16 l1 = __float2bfloat16(v.y - __bfloat162float(h1));
    __nv_bfloat16 l2 = __float2bfloat16(v.z - __bfloat162float(h2));
    __nv_bfloat16 l3 = __float2bfloat16(v.w - __bfloat162float(h3));
    __nv_bfloat162 ph0; ph0.x = h0; ph0.y = h1;
    __nv_bfloat162 ph1; ph1.x = h2; ph1.y = h3;
    __nv_bfloat162 pl0; pl0.x = l0; pl0.y = l1;
    __nv_bfloat162 pl1; pl1.x = l2; pl1.y = l3;
    ((__nv_bfloat162*)hi)[2*i]   = ph0;
    ((__nv_bfloat162*)hi)[2*i+1] = ph1;
    ((__nv_bfloat162*)lo)[2*i]   = pl0;
    ((__nv_bfloat162*)lo)[2*i+1] = pl1;
}

// ---------------- mma.sync bf16-split GEMM: C = A @ W^T + bias (+SiLU) -------
// CTA 128x128, 256 threads (8 warps: 4 M x 2 N). 3 products AhBh+AhBl+AlBh.
// C row stride = cstride; SiLU applied when n0 >= siluFrom.
#define GROW 80
#define TILEB (128*GROW)
__global__ void __launch_bounds__(256, 2) gemm_mma(
    const __nv_bfloat16* __restrict__ Ah, const __nv_bfloat16* __restrict__ Al,
    const __nv_bfloat16* __restrict__ Wh, const __nv_bfloat16* __restrict__ Wl,
    const float* __restrict__ bias, float* __restrict__ C,
    int cstride, int siluFrom)
{
    extern __shared__ char dsm[];
    const int tid  = threadIdx.x;
    const int wid  = tid >> 5;
    const int lane = tid & 31;
    const int wm = wid >> 1;
    const int wn = wid & 1;
    const int m0 = blockIdx.x * 128;
    const int n0 = blockIdx.y * 128;

    unsigned int sb = smem_u32_(dsm);
    const __nv_bfloat16* gsrc[4] = {Ah, Al, Wh, Wl};
    const int gbase[4] = {m0, m0, n0, n0};

    auto stage = [&](int kc, int buf) {
        unsigned int bb = sb + buf * (4 * TILEB);
        #pragma unroll
        for (int it = 0; it < 8; it++) {
            int i = tid + it * 256;
            int tile = i >> 9;
            int j = i & 511;
            int row = j >> 2, seg = j & 3;
            cpasync16_(bb + tile * TILEB + row * GROW + seg * 16,
                       gsrc[tile] + (size_t)(gbase[tile] + row) * DIM + kc * 32 + seg * 8);
        }
        asm volatile("cp.async.commit_group;" ::: "memory");
    };

    stage(0, 0);

    float acc[2][8][4];
    #pragma unroll
    for (int mt = 0; mt < 2; mt++)
        #pragma unroll
        for (int nt = 0; nt < 8; nt++)
            #pragma unroll
            for (int c = 0; c < 4; c++) acc[mt][nt][c] = 0.f;

    const int arow = wm * 32 + (lane & 15);
    const int acol = (lane >> 4) * 16;
    const int brow = wn * 64 + (lane & 7) + (((lane >> 4) & 1) << 3);
    const int bcol = ((lane >> 3) & 1) * 16;

    #pragma unroll 1
    for (int kc = 0; kc < 16; ++kc) {
        asm volatile("cp.async.wait_group 0;" ::: "memory");
        __syncthreads();
        if (kc + 1 < 16) stage(kc + 1, (kc + 1) & 1);

        unsigned int bb = sb + (kc & 1) * (4 * TILEB);
        unsigned int tAh = bb, tAl = bb + TILEB, tWh = bb + 2*TILEB, tWl = bb + 3*TILEB;

        #pragma unroll
        for (int ks = 0; ks < 2; ks++) {
            unsigned ah[2][4], al[2][4];
            #pragma unroll
            for (int mt = 0; mt < 2; mt++) {
                unsigned aoff = (arow + mt * 16) * GROW + ks * 32 + acol;
                ldsm4_(ah[mt][0], ah[mt][1], ah[mt][2], ah[mt][3], tAh + aoff);
                ldsm4_(al[mt][0], al[mt][1], al[mt][2], al[mt][3], tAl + aoff);
            }
            #pragma unroll
            for (int p = 0; p < 4; p++) {
                unsigned bh4[4], bl4[4];
                unsigned boff = (brow + p * 16) * GROW + ks * 32 + bcol;
                ldsm4_(bh4[0], bh4[1], bh4[2], bh4[3], tWh + boff);
                ldsm4_(bl4[0], bl4[1], bl4[2], bl4[3], tWl + boff);
                #pragma unroll
                for (int mt = 0; mt < 2; mt++) {
                    #pragma unroll
                    for (int sub = 0; sub < 2; sub++) {
                        float* ac = acc[mt][p * 2 + sub];
                        mma16816_(ac, ah[mt], &bh4[sub * 2]);
                        mma16816_(ac, ah[mt], &bl4[sub * 2]);
                        mma16816_(ac, al[mt], &bh4[sub * 2]);
                    }
                }
            }
        }
    }

    const int g = lane >> 2;
    const int cc = (lane & 3) * 2;
    const bool act = (n0 >= siluFrom);
    #pragma unroll
    for (int mt = 0; mt < 2; mt++) {
        #pragma unroll
        for (int nt = 0; nt < 8; nt++) {
            int col = n0 + wn * 64 + nt * 8 + cc;
            float2 bv = *(const float2*)(bias + col);
            int row0 = m0 + wm * 32 + mt * 16 + g;
            float c0 = acc[mt][nt][0] + bv.x;
            float c1 = acc[mt][nt][1] + bv.y;
            float c2 = acc[mt][nt][2] + bv.x;
            float c3 = acc[mt][nt][3] + bv.y;
            if (act) { c0 = silu_(c0); c1 = silu_(c1); c2 = silu_(c2); c3 = silu_(c3); }
            *(float2*)(C + (size_t)row0 * cstride + col)       = make_float2(c0, c1);
            *(float2*)(C + (size_t)(row0 + 8) * cstride + col) = make_float2(c2, c3);
        }
    }
}

// ---------------- alpha/beta GEMV + sigmoid ----------------
__global__ void __launch_bounds__(256) ab_kernel(
    const float* __restrict__ x,
    const float* __restrict__ Wa, const float* __restrict__ ba,
    const float* __restrict__ Wb, const float* __restrict__ bb,
    float* __restrict__ alpha, float* __restrict__ beta)
{
    const int warp = threadIdx.x >> 5, lane = threadIdx.x & 31;
    const int m = blockIdx.x * 8 + warp;
    const float* xr = x + (size_t)m * DIM;
    float sa = 0.f, sb = 0.f;
    #pragma unroll
    for (int i = 0; i < 4; i++) {
        float4 xv = *(const float4*)(xr + i * 128 + (lane << 2));
        float4 wa = *(const float4*)(Wa + i * 128 + (lane << 2));
        float4 wb = *(const float4*)(Wb + i * 128 + (lane << 2));
        sa += xv.x*wa.x + xv.y*wa.y + xv.z*wa.z + xv.w*wa.w;
        sb += xv.x*wb.x + xv.y*wb.y + xv.z*wb.z + xv.w*wb.w;
    }
    sa = wredsum_(sa);
    sb = wredsum_(sb);
    if (lane == 0) {
        alpha[m] = 1.0f / (1.0f + __expf(-(sa + ba[0])));
        beta[m]  = 1.0f / (1.0f + __expf(-(sb + bb[0])));
    }
}

// ---------------- depthwise causal conv(4) + SiLU (+ optional L2 norm) -------
// lin has row stride lstride (points at section base within g_qkvg).
__global__ void __launch_bounds__(128) conv_silu_kernel(
    const float* __restrict__ lin, const float* __restrict__ cw,
    const float* __restrict__ cb, float* __restrict__ outp, int do_l2,
    int lstride)
{
    __shared__ float red[4];
    const int m = blockIdx.x;
    const int s = m & (SLEN - 1);
    const int c = threadIdx.x << 2;
    const int lane = threadIdx.x & 31;
    const int warp = threadIdx.x >> 5;

    float w[4][4];
    #pragma unroll
    for (int ch = 0; ch < 4; ++ch) {
        float4 wv = *(const float4*)(cw + (size_t)(c + ch) * 4);
        w[ch][0] = wv.x; w[ch][1] = wv.y; w[ch][2] = wv.z; w[ch][3] = wv.w;
    }
    float4 bv = *(const float4*)(cb + c);
    float y0 = bv.x, y1 = bv.y, y2 = bv.z, y3 = bv.w;
    #pragma unroll
    for (int tau = 0; tau < 4; ++tau) {
        int sp = s - 3 + tau;
        if (sp >= 0) {
            float4 xv = *(const float4*)(lin + (size_t)(m - 3 + tau) * lstride + c);
            y0 += w[0][tau] * xv.x;
            y1 += w[1][tau] * xv.y;
            y2 += w[2][tau] * xv.z;
            y3 += w[3][tau] * xv.w;
        }
    }
    y0 = silu_(y0); y1 = silu_(y1); y2 = silu_(y2); y3 = silu_(y3);
    float sc = 1.0f;
    if (do_l2) {
        float ss = wredsum_(y0*y0 + y1*y1 + y2*y2 + y3*y3);
        if (lane == 0) red[warp] = ss;
        __syncthreads();
        float tot = red[0] + red[1] + red[2] + red[3];
        sc = 1.0f / fmaxf(sqrtf(tot), 1e-12f);
    }
    *(float4*)(outp + (size_t)m * DIM + c) = make_float4(y0*sc, y1*sc, y2*sc, y3*sc);
}

// ---------------- gated delta-rule scan (2 steps fused) ----------------------
__global__ void __launch_bounds__(64, 6) scan_kernel(
    const float* __restrict__ qn, const float* __restrict__ kn,
    const float* __restrict__ vn, const float* __restrict__ alpha,
    const float* __restrict__ beta, float* __restrict__ outp)
{
    const int tid  = threadIdx.x;
    const int warp = tid >> 5;
    const int lane = tid & 31;
    const int cta  = blockIdx.x;
    const int b    = cta >> 6;
    const int i0   = ((cta & 63) << 3) + (warp << 2);

    const float* kp = kn + (size_t)b * SLEN * DIM;
    const float* qp = qn + (size_t)b * SLEN * DIM;
    const float* vp = vn + (size_t)b * SLEN * DIM + i0;
    const float* ap = alpha + (size_t)b * SLEN;
    const float* bp = beta  + (size_t)b * SLEN;
    float* op = outp + (size_t)b * SLEN * DIM + i0;

    __shared__ __align__(16) float sbuf[3][2048];
    unsigned int sbase = smem_u32_(sbuf);
    const int sec = tid >> 4;
    const int t16 = tid & 15;
    const float* gsecN = ((sec & 1) ? qp : kp) + (sec >> 1) * DIM + t16 * 4;
    const unsigned int soff = sec * 2048 + t16 * 16;

    #pragma unroll
    for (int m = 0; m < 8; m++)
        cpasync16_(sbase + soff + m * 256, gsecN + m * 64);
    asm volatile("cp.async.commit_group;" ::: "memory");
    #pragma unroll
    for (int m = 0; m < 8; m++)
        cpasync16_(sbase + 8192 + soff + m * 256, gsecN + 2 * DIM + m * 64);
    asm volatile("cp.async.commit_group;" ::: "memory");

    unsigned long long z[4][8];
    #pragma unroll
    for (int r = 0; r < 4; r++)
        #pragma unroll
        for (int e = 0; e < 8; e++) z[r][e] = 0ULL;

    float A = 1.0f;
    const unsigned FULL = 0xffffffffu;
    int cur = 0, nxt = 2;

    const bool isout = (lane & 3) == 2;
    const int ostep = (lane >> 2) & 1;
    const int orow = ((lane >> 4) & 1) + (((lane >> 3) & 1) << 1);

    #pragma unroll 1
    for (int i = 0; i < SLEN / 2; ++i) {
        asm volatile("cp.async.wait_group 1;" ::: "memory");
        __syncthreads();
        if (i + 2 < SLEN / 2) {
            const float* gs2 = gsecN + (size_t)(2 * i + 4) * DIM;
            #pragma unroll
            for (int m = 0; m < 8; m++)
                cpasync16_(sbase + nxt * 8192 + soff + m * 256, gs2 + m * 64);
        }
        asm volatile("cp.async.commit_group;" ::: "memory");

        unsigned long long kc0[8], qc0[8], kc1[8], qc1[8];
        {
            const float4* f0 = (const float4*)&sbuf[cur][0];
            const float4* f1 = (const float4*)&sbuf[cur][512];
            const float4* f2 = (const float4*)&sbuf[cur][1024];
            const float4* f3 = (const float4*)&sbuf[cur][1536];
            #pragma unroll
            for (int m = 0; m < 4; m++) {
                float4 u;
                u = f0[m * 32 + lane]; kc0[2*m] = pk2_(u.x,u.y); kc0[2*m+1] = pk2_(u.z,u.w);
                u = f1[m * 32 + lane]; qc0[2*m] = pk2_(u.x,u.y); qc0[2*m+1] = pk2_(u.z,u.w);
                u = f2[m * 32 + lane]; kc1[2*m] = pk2_(u.x,u.y); kc1[2*m+1] = pk2_(u.z,u.w);
                u = f3[m * 32 + lane]; qc1[2*m] = pk2_(u.x,u.y); qc1[2*m+1] = pk2_(u.z,u.w);
            }
        }
        float4 v0 = *(const float4*)(vp + (size_t)(2 * i) * DIM);
        float4 v1 = *(const float4*)(vp + (size_t)(2 * i + 1) * DIM);
        float2 a2 = *(const float2*)(ap + 2 * i);
        float2 b2 = *(const float2*)(bp + 2 * i);

        unsigned long long zka[4] = {0,0,0,0}, zqa[4] = {0,0,0,0};
        unsigned long long zkb[4] = {0,0,0,0}, zqb[4] = {0,0,0,0};
        unsigned long long c00a = 0, c01a = 0, cka = 0, c11a = 0;
        #pragma unroll
        for (int e = 0; e < 8; e++) {
            #pragma unroll
            for (int r = 0; r < 4; r++) {
                zka[r] = fma2_(z[r][e], kc0[e], zka[r]);
                zqa[r] = fma2_(z[r][e], qc0[e], zqa[r]);
                zkb[r] = fma2_(z[r][e], kc1[e], zkb[r]);
                zqb[r] = fma2_(z[r][e], qc1[e], zqb[r]);
            }
            c00a = fma2_(kc0[e], qc0[e], c00a);
            c01a = fma2_(kc0[e], qc1[e], c01a);
            cka  = fma2_(kc0[e], kc1[e], cka);
            c11a = fma2_(kc1[e], qc1[e], c11a);
        }
        float d[16];
        d[0]=hadd2_(zka[0]); d[1]=hadd2_(zka[1]); d[2]=hadd2_(zka[2]); d[3]=hadd2_(zka[3]);
        d[4]=hadd2_(zkb[0]); d[5]=hadd2_(zkb[1]); d[6]=hadd2_(zkb[2]); d[7]=hadd2_(zkb[3]);
        d[8]=hadd2_(zqa[0]); d[9]=hadd2_(zqa[1]); d[10]=hadd2_(zqa[2]); d[11]=hadd2_(zqa[3]);
        d[12]=hadd2_(zqb[0]); d[13]=hadd2_(zqb[1]); d[14]=hadd2_(zqb[2]); d[15]=hadd2_(zqb[3]);
        float f;
        {
            float x[16];
            #pragma unroll
            for (int j = 0; j < 16; j++) x[j] = d[j] + __shfl_xor_sync(FULL, d[j], 16);
            bool s4 = (lane & 16) != 0;
            float w8[8];
            #pragma unroll
            for (int j = 0; j < 8; j++) w8[j] = s4 ? x[2*j+1] : x[2*j];
            float y8[8];
            #pragma unroll
            for (int j = 0; j < 8; j++) y8[j] = w8[j] + __shfl_xor_sync(FULL, w8[j], 8);
            bool s3 = (lane & 8) != 0;
            float u4[4];
            #pragma unroll
            for (int j = 0; j < 4; j++) u4[j] = s3 ? y8[2*j+1] : y8[2*j];
            float t4[4];
            #pragma unroll
            for (int j = 0; j < 4; j++) t4[j] = u4[j] + __shfl_xor_sync(FULL, u4[j], 4);
            bool s2 = (lane & 4) != 0;
            float sv[2];
            sv[0] = s2 ? t4[1] : t4[0];
            sv[1] = s2 ? t4[3] : t4[2];
            float rv[2];
            rv[0] = sv[0] + __shfl_xor_sync(FULL, sv[0], 2);
            rv[1] = sv[1] + __shfl_xor_sync(FULL, sv[1], 2);
            float qv = (lane & 2) ? rv[1] : rv[0];
            f = qv + __shfl_xor_sync(FULL, qv, 1);
        }
        float c00, c01, ck, c11;
        {
            float e0 = hadd2_(c00a), e1 = hadd2_(c01a), e2 = hadd2_(cka), e3 = hadd2_(c11a);
            float x0 = e0 + __shfl_xor_sync(FULL, e0, 16);
            float x1 = e1 + __shfl_xor_sync(FULL, e1, 16);
            float x2 = e2 + __shfl_xor_sync(FULL, e2, 16);
            float x3 = e3 + __shfl_xor_sync(FULL, e3, 16);
            bool s4 = (lane & 16) != 0;
            float g0 = s4 ? x1 : x0;
            float g1 = s4 ? x3 : x2;
            float y0 = g0 + __shfl_xor_sync(FULL, g0, 8);
            float y1 = g1 + __shfl_xor_sync(FULL, g1, 8);
            float h = (lane & 8) ? y1 : y0;
            h += __shfl_xor_sync(FULL, h, 4);
            h += __shfl_xor_sync(FULL, h, 2);
            h += __shfl_xor_sync(FULL, h, 1);
            c00 = __shfl_sync(FULL, h, 0);
            c01 = __shfl_sync(FULL, h, 16);
            ck  = __shfl_sync(FULL, h, 8);
            c11 = __shfl_sync(FULL, h, 24);
        }
        float zk0r[4], zk1r[4];
        zk0r[0] = __shfl_sync(FULL, f, 0);
        zk0r[1] = __shfl_sync(FULL, f, 16);
        zk0r[2] = __shfl_sync(FULL, f, 8);
        zk0r[3] = __shfl_sync(FULL, f, 24);
        zk1r[0] = __shfl_sync(FULL, f, 4);
        zk1r[1] = __shfl_sync(FULL, f, 20);
        zk1r[2] = __shfl_sync(FULL, f, 12);
        zk1r[3] = __shfl_sync(FULL, f, 28);

        float A1 = A * a2.x;
        float rA1 = 1.0f / A1;
        float ab0 = a2.x * b2.x;
        float vv0[4] = {v0.x, v0.y, v0.z, v0.w};
        float vv1[4] = {v1.x, v1.y, v1.z, v1.w};
        float w0v[4], w1v[4];
        #pragma unroll
        for (int r = 0; r < 4; r++)
            w0v[r] = (b2.x * vv0[r] - ab0 * (A * zk0r[r])) * rA1;
        float A2f = A1 * a2.y;
        float rA2 = 1.0f / A2f;
        float ab1 = a2.y * b2.y;
        #pragma unroll
        for (int r = 0; r < 4; r++) {
            float sk1 = A1 * (zk1r[r] + w0v[r] * ck);
            w1v[r] = (b2.y * vv1[r] - ab1 * sk1) * rA2;
        }

        #pragma unroll
        for (int r = 0; r < 4; r++) {
            unsigned long long W0 = pk2_(w0v[r], w0v[r]);
            unsigned long long W1 = pk2_(w1v[r], w1v[r]);
            #pragma unroll
            for (int e = 0; e < 8; e++)
                z[r][e] = fma2_(W1, kc1[e], fma2_(W0, kc0[e], z[r][e]));
        }

        if (isout) {
            float o;
            if (ostep == 0) o = A1 * (f + w0v[orow] * c00);
            else            o = A2f * (f + w0v[orow] * c01 + w1v[orow] * c11);
            op[(size_t)(2 * i + ostep) * DIM + orow] = o;
        }

        A = A2f;
        if ((i & 7) == 7) {
            unsigned long long AA = pk2_(A, A);
            #pragma unroll
            for (int r = 0; r < 4; r++)
                #pragma unroll
                for (int e = 0; e < 8; e++) z[r][e] = mul2_(z[r][e], AA);
            A = 1.0f;
        }

        cur = (cur == 2) ? 0 : cur + 1;
        nxt = (nxt == 2) ? 0 : nxt + 1;
    }
}

// ---------------- zero-centered RMSNorm * gate -> bf16 hi/lo split -----------
__global__ void __launch_bounds__(128) norm_gate_kernel(
    const float* __restrict__ gdn, const float* __restrict__ norm_w,
    const float* __restrict__ gate, int gstride,
    __nv_bfloat16* __restrict__ fhi, __nv_bfloat16* __restrict__ flo)
{
    __shared__ float rs[4], rq[4];
    const int m = blockIdx.x;
    const int c = threadIdx.x << 2;
    const int lane = threadIdx.x & 31;
    const int warp = threadIdx.x >> 5;

    float4 xv = *(const float4*)(gdn + (size_t)m * DIM + c);
    float s = wredsum_(xv.x + xv.y + xv.z + xv.w);
    float q = wredsum_(xv.x*xv.x + xv.y*xv.y + xv.z*xv.z + xv.w*xv.w);
    if (lane == 0) { rs[warp] = s; rq[warp] = q; }
    __syncthreads();
    float sum = rs[0] + rs[1] + rs[2] + rs[3];
    float sq  = rq[0] + rq[1] + rq[2] + rq[3];
    float mean = sum * (1.0f / DIM);
    float var  = sq * (1.0f / DIM) - mean * mean;
    float inv  = rsqrtf(var + 1e-5f);

    float4 wv = *(const float4*)(norm_w + c);
    float4 gv = *(const float4*)(gate + (size_t)m * gstride + c);
    float r0 = (xv.x - mean) * inv * wv.x * gv.x;
    float r1 = (xv.y - mean) * inv * wv.y * gv.y;
    float r2 = (xv.z - mean) * inv * wv.z * gv.z;
    float r3 = (xv.w - mean) * inv * wv.w * gv.w;

    __nv_bfloat16 h0 = __float2bfloat16(r0), h1 = __float2bfloat16(r1);
    __nv_bfloat16 h2 = __float2bfloat16(r2), h3 = __float2bfloat16(r3);
    __nv_bfloat16 l0 = __float2bfloat16(r0 - __bfloat162float(h0));
    __nv_bfloat16 l1 = __float2bfloat16(r1 - __bfloat162float(h1));
    __nv_bfloat16 l2 = __float2bfloat16(r2 - __bfloat162float(h2));
    __nv_bfloat16 l3 = __float2bfloat16(r3 - __bfloat162float(h3));
    size_t idx = (size_t)m * DIM + c;
    __nv_bfloat162 ph0; ph0.x = h0; ph0.y = h1;
    __nv_bfloat162 ph1; ph1.x = h2; ph1.y = h3;
    __nv_bfloat162 pl0; pl0.x = l0; pl0.y = l1;
    __nv_bfloat162 pl1; pl1.x = l2; pl1.y = l3;
    ((__nv_bfloat162*)(fhi + idx))[0] = ph0;
    ((__nv_bfloat162*)(fhi + idx))[1] = ph1;
    ((__nv_bfloat162*)(flo + idx))[0] = pl0;
    ((__nv_bfloat162*)(flo + idx))[1] = pl1;
}

// ---------------- launch ----------------
extern "C" void kernel_launch(void* const* d_in, const int* in_sizes, int n_in,
                              void* d_out, int out_size) {
    const float* x    = (const float*)d_in[0];
    const float* Wq   = (const float*)d_in[1];
    const float* bq   = (const float*)d_in[2];
    const float* Wk   = (const float*)d_in[3];
    const float* bk   = (const float*)d_in[4];
    const float* Wv   = (const float*)d_in[5];
    const float* bv   = (const float*)d_in[6];
    const float* Wa   = (const float*)d_in[7];
    const float* ba   = (const float*)d_in[8];
    const float* Wb   = (const float*)d_in[9];
    const float* bb   = (const float*)d_in[10];
    const float* cwq  = (const float*)d_in[11];
    const float* cbq  = (const float*)d_in[12];
    const float* cwk  = (const float*)d_in[13];
    const float* cbk  = (const float*)d_in[14];
    const float* cwv  = (const float*)d_in[15];
    const float* cbv  = (const float*)d_in[16];
    const float* norm_w = (const float*)d_in[17];
    const float* Wg   = (const float*)d_in[18];
    const float* bg   = (const float*)d_in[19];
    const float* Wo   = (const float*)d_in[20];
    const float* bo   = (const float*)d_in[21];
    float* out = (float*)d_out;

    float *qkvg, *qn, *kn, *vn, *gdn, *al, *be, *bias4;
    __nv_bfloat16 *xhi, *xlo, *fhi, *flo, *whi, *wlo;
    cudaGetSymbolAddress((void**)&qkvg, g_qkvg);
    cudaGetSymbolAddress((void**)&qn,   g_q);
    cudaGetSymbolAddress((void**)&kn,   g_k);
    cudaGetSymbolAddress((void**)&vn,   g_v);
    cudaGetSymbolAddress((void**)&gdn,  g_gdn);
    cudaGetSymbolAddress((void**)&al,   g_alpha);
    cudaGetSymbolAddress((void**)&be,   g_beta);
    cudaGetSymbolAddress((void**)&bias4, g_bias4);
    cudaGetSymbolAddress((void**)&xhi,  g_xhi);
    cudaGetSymbolAddress((void**)&xlo,  g_xlo);
    cudaGetSymbolAddress((void**)&fhi,  g_fhi);
    cudaGetSymbolAddress((void**)&flo,  g_flo);
    cudaGetSymbolAddress((void**)&whi,  g_whi);
    cudaGetSymbolAddress((void**)&wlo,  g_wlo);

    const int GEMM_SMEM = 2 * 4 * TILEB;  // 81920
    cudaFuncSetAttribute(gemm_mma, cudaFuncAttributeMaxDynamicSharedMemorySize, GEMM_SMEM);

    // launches 1-5 (so ncu -s 5 -c 1 captures the fused GEMM at launch 6)
    pack_bias_kernel<<<NQKVG/256, 256>>>(bq, bk, bv, bg, bias4);            // 1
    convert_split_kernel<<<MTOT*DIM/4/256, 256>>>(x, xhi, xlo, MTOT*DIM/4); // 2
    // weights: Wq,Wk,Wv,Wg stacked at whi[0..4*D*D), Wo at whi[4*D*D..)
    convert_split_kernel<<<2*DIM*DIM/4/256, 256>>>(Wq, whi, wlo, DIM*DIM/4);            // 3 (Wq)
    // note: convert Wk,Wv,Wg,Wo in two more launches
    convert_split_kernel<<<3*DIM*DIM/4/256, 256>>>(Wk, whi + DIM*DIM, wlo + DIM*DIM, DIM*DIM/4); // 4
    ab_kernel<<<MTOT / 8, 256>>>(x, Wa, ba, Wb, bb, al, be);                // 5
    convert_split_kernel<<<DIM*DIM/4/256, 256>>>(Wv, whi + 2*DIM*DIM, wlo + 2*DIM*DIM, DIM*DIM/4);
    convert_split_kernel<<<DIM*DIM/4/256, 256>>>(Wg, whi + 3*DIM*DIM, wlo + 3*DIM*DIM, DIM*DIM/4);
    convert_split_kernel<<<DIM*DIM/4/256, 256>>>(Wo, whi + 4*DIM*DIM, wlo + 4*DIM*DIM, DIM*DIM/4);

    // fused Q|K|V|G GEMM: N = 2048
    dim3 gg4(MTOT/128, NQKVG/128);
    gemm_mma<<<gg4, 256, GEMM_SMEM>>>(xhi, xlo, whi, wlo, bias4, qkvg,
                                      NQKVG, 3*DIM);

    conv_silu_kernel<<<MTOT, 128>>>(qkvg + 0,     cwq, cbq, qn, 1, NQKVG);
    conv_silu_kernel<<<MTOT, 128>>>(qkvg + 512,   cwk, cbk, kn, 1, NQKVG);
    conv_silu_kernel<<<MTOT, 128>>>(qkvg + 1024,  cwv, cbv, vn, 0, NQKVG);

    scan_kernel<<<512, 64>>>(qn, kn, vn, al, be, gdn);

    norm_gate_kernel<<<MTOT, 128>>>(gdn, norm_w, qkvg + 1536, NQKVG, fhi, flo);
    dim3 ggo(MTOT/128, DIM/128);
    gemm_mma<<<ggo, 256, GEMM_SMEM>>>(fhi, flo, whi + 4*DIM*DIM, wlo + 4*DIM*DIM,
                                      bo, out, DIM, 1 << 30);
}

// round 17
// speedup vs baseline: 1.4850x; 1.0441x over previous
#include <cuda_runtime.h>
#include <cuda_bf16.h>
#include <math.h>

#define BATCH 8
#define SLEN  2048
#define DIM   512
#define MTOT  (BATCH*SLEN)
#define NQKVG 2048

// ---------------- scratch ----------------
__device__ float g_qkvg[(size_t)MTOT*NQKVG];
__device__ float g_q[MTOT*DIM];
__device__ float g_k[MTOT*DIM];
__device__ float g_v[MTOT*DIM];
__device__ float g_gdn[MTOT*DIM];
__device__ float g_alpha[MTOT];
__device__ float g_beta[MTOT];
__device__ float g_bias4[NQKVG];
__device__ __align__(16) __nv_bfloat16 g_xhi[MTOT*DIM];
__device__ __align__(16) __nv_bfloat16 g_xlo[MTOT*DIM];
__device__ __align__(16) __nv_bfloat16 g_fhi[MTOT*DIM];
__device__ __align__(16) __nv_bfloat16 g_flo[MTOT*DIM];
__device__ __align__(16) __nv_bfloat16 g_whi[5*DIM*DIM];
__device__ __align__(16) __nv_bfloat16 g_wlo[5*DIM*DIM];

// ---------------- helpers ----------------
__device__ __forceinline__ unsigned long long fma2_(unsigned long long a,
                                                    unsigned long long b,
                                                    unsigned long long c) {
    unsigned long long d;
    asm("fma.rn.f32x2 %0, %1, %2, %3;" : "=l"(d) : "l"(a), "l"(b), "l"(c));
    return d;
}
__device__ __forceinline__ unsigned long long mul2_(unsigned long long a,
                                                    unsigned long long b) {
    unsigned long long d;
    asm("mul.rn.f32x2 %0, %1, %2;" : "=l"(d) : "l"(a), "l"(b));
    return d;
}
__device__ __forceinline__ unsigned long long pk2_(float lo, float hi) {
    unsigned long long r;
    asm("mov.b64 %0, {%1, %2};" : "=l"(r)
        : "r"(__float_as_uint(lo)), "r"(__float_as_uint(hi)));
    return r;
}
__device__ __forceinline__ float hadd2_(unsigned long long a) {
    unsigned int l, h;
    asm("mov.b64 {%0, %1}, %2;" : "=r"(l), "=r"(h) : "l"(a));
    return __uint_as_float(l) + __uint_as_float(h);
}
__device__ __forceinline__ float wredsum_(float v) {
    #pragma unroll
    for (int off = 16; off; off >>= 1) v += __shfl_xor_sync(0xffffffffu, v, off);
    return v;
}
__device__ __forceinline__ float silu_(float x) { return x / (1.0f + __expf(-x)); }
__device__ __forceinline__ void cpasync16_(unsigned int dst, const void* src) {
    asm volatile("cp.async.cg.shared.global [%0], [%1], 16;"
                 :: "r"(dst), "l"(src) : "memory");
}
__device__ __forceinline__ unsigned int smem_u32_(const void* p) {
    unsigned int a;
    asm("{ .reg .u64 t; cvta.to.shared.u64 t, %1; cvt.u32.u64 %0, t; }"
        : "=r"(a) : "l"(p));
    return a;
}
__device__ __forceinline__ void ldsm4_(unsigned& r0, unsigned& r1, unsigned& r2,
                                       unsigned& r3, unsigned addr) {
    asm volatile("ldmatrix.sync.aligned.m8n8.x4.shared.b16 {%0,%1,%2,%3}, [%4];"
                 : "=r"(r0), "=r"(r1), "=r"(r2), "=r"(r3) : "r"(addr));
}
__device__ __forceinline__ void mma16816_(float* d, const unsigned* a,
                                          const unsigned* b) {
    asm volatile(
        "mma.sync.aligned.m16n8k16.row.col.f32.bf16.bf16.f32 "
        "{%0,%1,%2,%3}, {%4,%5,%6,%7}, {%8,%9}, {%0,%1,%2,%3};"
        : "+f"(d[0]), "+f"(d[1]), "+f"(d[2]), "+f"(d[3])
        : "r"(a[0]), "r"(a[1]), "r"(a[2]), "r"(a[3]), "r"(b[0]), "r"(b[1]));
}

// ---------------- bias pack ----------------
__global__ void pack_bias_kernel(const float* bq, const float* bk,
                                 const float* bv, const float* bg,
                                 float* out) {
    int i = blockIdx.x * 256 + threadIdx.x;
    if (i >= NQKVG) return;
    const float* src = (i < 512) ? bq : (i < 1024) ? bk : (i < 1536) ? bv : bg;
    out[i] = src[i & 511];
}

// ---------------- fp32 -> bf16 hi/lo split (single src) ----------------
__device__ __forceinline__ void split_store_(const float* src,
    __nv_bfloat16* hi, __nv_bfloat16* lo, int i)
{
    float4 v = ((const float4*)src)[i];
    __nv_bfloat16 h0 = __float2bfloat16(v.x);
    __nv_bfloat16 h1 = __float2bfloat16(v.y);
    __nv_bfloat16 h2 = __float2bfloat16(v.z);
    __nv_bfloat16 h3 = __float2bfloat16(v.w);
    __nv_bfloat16 l0 = __float2bfloat16(v.x - __bfloat162float(h0));
    __nv_bfloat16 l1 = __float2bfloat16(v.y - __bfloat162float(h1));
    __nv_bfloat16 l2 = __float2bfloat16(v.z - __bfloat162float(h2));
    __nv_bfloat16 l3 = __float2bfloat16(v.w - __bfloat162float(h3));
    __nv_bfloat162 ph0; ph0.x = h0; ph0.y = h1;
    __nv_bfloat162 ph1; ph1.x = h2; ph1.y = h3;
    __nv_bfloat162 pl0; pl0.x = l0; pl0.y = l1;
    __nv_bfloat162 pl1; pl1.x = l2; pl1.y = l3;
    ((__nv_bfloat162*)hi)[2*i]   = ph0;
    ((__nv_bfloat162*)hi)[2*i+1] = ph1;
    ((__nv_bfloat162*)lo)[2*i]   = pl0;
    ((__nv_bfloat162*)lo)[2*i+1] = pl1;
}
__global__ void __launch_bounds__(256) convert_split_kernel(
    const float* __restrict__ src, __nv_bfloat16* __restrict__ hi,
    __nv_bfloat16* __restrict__ lo, int n4)
{
    int i = blockIdx.x * 256 + threadIdx.x;
    if (i >= n4) return;
    split_store_(src, hi, lo, i);
}
// fused 4-weight convert (one launch)
__global__ void __launch_bounds__(256) convert_w4_kernel(
    const float* __restrict__ w0s, const float* __restrict__ w1s,
    const float* __restrict__ w2s, const float* __restrict__ w3s,
    __nv_bfloat16* __restrict__ hi, __nv_bfloat16* __restrict__ lo)
{
    const int per = DIM * DIM / 4;           // float4s per weight
    int i = blockIdx.x * 256 + threadIdx.x;
    if (i >= 4 * per) return;
    int w = i / per, j = i - w * per;
    const float* src = (w == 0) ? w0s : (w == 1) ? w1s : (w == 2) ? w2s : w3s;
    split_store_(src, hi + (size_t)w * DIM * DIM, lo + (size_t)w * DIM * DIM, j);
}

// ---------------- mma.sync bf16-split GEMM ----------------
#define GROW 80
#define TILEB (128*GROW)
__global__ void __launch_bounds__(256, 2) gemm_mma(
    const __nv_bfloat16* __restrict__ Ah, const __nv_bfloat16* __restrict__ Al,
    const __nv_bfloat16* __restrict__ Wh, const __nv_bfloat16* __restrict__ Wl,
    const float* __restrict__ bias, float* __restrict__ C,
    int cstride, int siluFrom)
{
    extern __shared__ char dsm[];
    const int tid  = threadIdx.x;
    const int wid  = tid >> 5;
    const int lane = tid & 31;
    const int wm = wid >> 1;
    const int wn = wid & 1;
    const int m0 = blockIdx.x * 128;
    const int n0 = blockIdx.y * 128;

    unsigned int sb = smem_u32_(dsm);
    const __nv_bfloat16* gsrc[4] = {Ah, Al, Wh, Wl};
    const int gbase[4] = {m0, m0, n0, n0};

    auto stage = [&](int kc, int buf) {
        unsigned int bb = sb + buf * (4 * TILEB);
        #pragma unroll
        for (int it = 0; it < 8; it++) {
            int i = tid + it * 256;
            int tile = i >> 9;
            int j = i & 511;
            int row = j >> 2, seg = j & 3;
            cpasync16_(bb + tile * TILEB + row * GROW + seg * 16,
                       gsrc[tile] + (size_t)(gbase[tile] + row) * DIM + kc * 32 + seg * 8);
        }
        asm volatile("cp.async.commit_group;" ::: "memory");
    };

    stage(0, 0);

    float acc[2][8][4];
    #pragma unroll
    for (int mt = 0; mt < 2; mt++)
        #pragma unroll
        for (int nt = 0; nt < 8; nt++)
            #pragma unroll
            for (int c = 0; c < 4; c++) acc[mt][nt][c] = 0.f;

    const int arow = wm * 32 + (lane & 15);
    const int acol = (lane >> 4) * 16;
    const int brow = wn * 64 + (lane & 7) + (((lane >> 4) & 1) << 3);
    const int bcol = ((lane >> 3) & 1) * 16;

    #pragma unroll 1
    for (int kc = 0; kc < 16; ++kc) {
        asm volatile("cp.async.wait_group 0;" ::: "memory");
        __syncthreads();
        if (kc + 1 < 16) stage(kc + 1, (kc + 1) & 1);

        unsigned int bb = sb + (kc & 1) * (4 * TILEB);
        unsigned int tAh = bb, tAl = bb + TILEB, tWh = bb + 2*TILEB, tWl = bb + 3*TILEB;

        #pragma unroll
        for (int ks = 0; ks < 2; ks++) {
            unsigned ah[2][4], al[2][4];
            #pragma unroll
            for (int mt = 0; mt < 2; mt++) {
                unsigned aoff = (arow + mt * 16) * GROW + ks * 32 + acol;
                ldsm4_(ah[mt][0], ah[mt][1], ah[mt][2], ah[mt][3], tAh + aoff);
                ldsm4_(al[mt][0], al[mt][1], al[mt][2], al[mt][3], tAl + aoff);
            }
            #pragma unroll
            for (int p = 0; p < 4; p++) {
                unsigned bh4[4], bl4[4];
                unsigned boff = (brow + p * 16) * GROW + ks * 32 + bcol;
                ldsm4_(bh4[0], bh4[1], bh4[2], bh4[3], tWh + boff);
                ldsm4_(bl4[0], bl4[1], bl4[2], bl4[3], tWl + boff);
                #pragma unroll
                for (int mt = 0; mt < 2; mt++) {
                    #pragma unroll
                    for (int sub = 0; sub < 2; sub++) {
                        float* ac = acc[mt][p * 2 + sub];
                        mma16816_(ac, ah[mt], &bh4[sub * 2]);
                        mma16816_(ac, ah[mt], &bl4[sub * 2]);
                        mma16816_(ac, al[mt], &bh4[sub * 2]);
                    }
                }
            }
        }
    }

    const int g = lane >> 2;
    const int cc = (lane & 3) * 2;
    const bool act = (n0 >= siluFrom);
    #pragma unroll
    for (int mt = 0; mt < 2; mt++) {
        #pragma unroll
        for (int nt = 0; nt < 8; nt++) {
            int col = n0 + wn * 64 + nt * 8 + cc;
            float2 bv = *(const float2*)(bias + col);
            int row0 = m0 + wm * 32 + mt * 16 + g;
            float c0 = acc[mt][nt][0] + bv.x;
            float c1 = acc[mt][nt][1] + bv.y;
            float c2 = acc[mt][nt][2] + bv.x;
            float c3 = acc[mt][nt][3] + bv.y;
            if (act) { c0 = silu_(c0); c1 = silu_(c1); c2 = silu_(c2); c3 = silu_(c3); }
            *(float2*)(C + (size_t)row0 * cstride + col)       = make_float2(c0, c1);
            *(float2*)(C + (size_t)(row0 + 8) * cstride + col) = make_float2(c2, c3);
        }
    }
}

// ---------------- alpha/beta GEMV + sigmoid ----------------
__global__ void __launch_bounds__(256) ab_kernel(
    const float* __restrict__ x,
    const float* __restrict__ Wa, const float* __restrict__ ba,
    const float* __restrict__ Wb, const float* __restrict__ bb,
    float* __restrict__ alpha, float* __restrict__ beta)
{
    const int warp = threadIdx.x >> 5, lane = threadIdx.x & 31;
    const int m = blockIdx.x * 8 + warp;
    const float* xr = x + (size_t)m * DIM;
    float sa = 0.f, sb = 0.f;
    #pragma unroll
    for (int i = 0; i < 4; i++) {
        float4 xv = *(const float4*)(xr + i * 128 + (lane << 2));
        float4 wa = *(const float4*)(Wa + i * 128 + (lane << 2));
        float4 wb = *(const float4*)(Wb + i * 128 + (lane << 2));
        sa += xv.x*wa.x + xv.y*wa.y + xv.z*wa.z + xv.w*wa.w;
        sb += xv.x*wb.x + xv.y*wb.y + xv.z*wb.z + xv.w*wb.w;
    }
    sa = wredsum_(sa);
    sb = wredsum_(sb);
    if (lane == 0) {
        alpha[m] = 1.0f / (1.0f + __expf(-(sa + ba[0])));
        beta[m]  = 1.0f / (1.0f + __expf(-(sb + bb[0])));
    }
}

// ---------------- fused depthwise conv(4) + SiLU (+L2 for q,k) --------------
// gridDim.y = 3 sections (0:q,1:k,2:v) reading qkvg columns sec*512.
__global__ void __launch_bounds__(128) conv_fused_kernel(
    const float* __restrict__ qkvg,
    const float* __restrict__ cwq, const float* __restrict__ cbq,
    const float* __restrict__ cwk, const float* __restrict__ cbk,
    const float* __restrict__ cwv, const float* __restrict__ cbv,
    float* __restrict__ qo, float* __restrict__ ko, float* __restrict__ vo)
{
    __shared__ float red[4];
    const int sec = blockIdx.y;
    const float* lin = qkvg + sec * 512;
    const float* cw  = (sec == 0) ? cwq : (sec == 1) ? cwk : cwv;
    const float* cb  = (sec == 0) ? cbq : (sec == 1) ? cbk : cbv;
    float* outp      = (sec == 0) ? qo  : (sec == 1) ? ko  : vo;
    const int do_l2  = (sec < 2);

    const int m = blockIdx.x;
    const int s = m & (SLEN - 1);
    const int c = threadIdx.x << 2;
    const int lane = threadIdx.x & 31;
    const int warp = threadIdx.x >> 5;

    float w[4][4];
    #pragma unroll
    for (int ch = 0; ch < 4; ++ch) {
        float4 wv = *(const float4*)(cw + (size_t)(c + ch) * 4);
        w[ch][0] = wv.x; w[ch][1] = wv.y; w[ch][2] = wv.z; w[ch][3] = wv.w;
    }
    float4 bv = *(const float4*)(cb + c);
    float y0 = bv.x, y1 = bv.y, y2 = bv.z, y3 = bv.w;
    #pragma unroll
    for (int tau = 0; tau < 4; ++tau) {
        int sp = s - 3 + tau;
        if (sp >= 0) {
            float4 xv = *(const float4*)(lin + (size_t)(m - 3 + tau) * NQKVG + c);
            y0 += w[0][tau] * xv.x;
            y1 += w[1][tau] * xv.y;
            y2 += w[2][tau] * xv.z;
            y3 += w[3][tau] * xv.w;
        }
    }
    y0 = silu_(y0); y1 = silu_(y1); y2 = silu_(y2); y3 = silu_(y3);
    float sc = 1.0f;
    if (do_l2) {
        float ss = wredsum_(y0*y0 + y1*y1 + y2*y2 + y3*y3);
        if (lane == 0) red[warp] = ss;
        __syncthreads();
        float tot = red[0] + red[1] + red[2] + red[3];
        sc = 1.0f / fmaxf(sqrtf(tot), 1e-12f);
    }
    *(float4*)(outp + (size_t)m * DIM + c) = make_float4(y0*sc, y1*sc, y2*sc, y3*sc);
}

// ---------------- gated delta-rule scan (2 steps fused) ----------------------
__global__ void __launch_bounds__(64, 6) scan_kernel(
    const float* __restrict__ qn, const float* __restrict__ kn,
    const float* __restrict__ vn, const float* __restrict__ alpha,
    const float* __restrict__ beta, float* __restrict__ outp)
{
    const int tid  = threadIdx.x;
    const int warp = tid >> 5;
    const int lane = tid & 31;
    const int cta  = blockIdx.x;
    const int b    = cta >> 6;
    const int i0   = ((cta & 63) << 3) + (warp << 2);

    const float* kp = kn + (size_t)b * SLEN * DIM;
    const float* qp = qn + (size_t)b * SLEN * DIM;
    const float* vp = vn + (size_t)b * SLEN * DIM + i0;
    const float* ap = alpha + (size_t)b * SLEN;
    const float* bp = beta  + (size_t)b * SLEN;
    float* op = outp + (size_t)b * SLEN * DIM + i0;

    __shared__ __align__(16) float sbuf[3][2048];
    unsigned int sbase = smem_u32_(sbuf);
    const int sec = tid >> 4;
    const int t16 = tid & 15;
    const float* gsecN = ((sec & 1) ? qp : kp) + (sec >> 1) * DIM + t16 * 4;
    const unsigned int soff = sec * 2048 + t16 * 16;

    #pragma unroll
    for (int m = 0; m < 8; m++)
        cpasync16_(sbase + soff + m * 256, gsecN + m * 64);
    asm volatile("cp.async.commit_group;" ::: "memory");
    #pragma unroll
    for (int m = 0; m < 8; m++)
        cpasync16_(sbase + 8192 + soff + m * 256, gsecN + 2 * DIM + m * 64);
    asm volatile("cp.async.commit_group;" ::: "memory");

    unsigned long long z[4][8];
    #pragma unroll
    for (int r = 0; r < 4; r++)
        #pragma unroll
        for (int e = 0; e < 8; e++) z[r][e] = 0ULL;

    float A = 1.0f;
    const unsigned FULL = 0xffffffffu;
    int cur = 0, nxt = 2;

    const bool isout = (lane & 3) == 2;
    const int ostep = (lane >> 2) & 1;
    const int orow = ((lane >> 4) & 1) + (((lane >> 3) & 1) << 1);

    #pragma unroll 1
    for (int i = 0; i < SLEN / 2; ++i) {
        asm volatile("cp.async.wait_group 1;" ::: "memory");
        __syncthreads();
        if (i + 2 < SLEN / 2) {
            const float* gs2 = gsecN + (size_t)(2 * i + 4) * DIM;
            #pragma unroll
            for (int m = 0; m < 8; m++)
                cpasync16_(sbase + nxt * 8192 + soff + m * 256, gs2 + m * 64);
        }
        asm volatile("cp.async.commit_group;" ::: "memory");

        unsigned long long kc0[8], qc0[8], kc1[8], qc1[8];
        {
            const float4* f0 = (const float4*)&sbuf[cur][0];
            const float4* f1 = (const float4*)&sbuf[cur][512];
            const float4* f2 = (const float4*)&sbuf[cur][1024];
            const float4* f3 = (const float4*)&sbuf[cur][1536];
            #pragma unroll
            for (int m = 0; m < 4; m++) {
                float4 u;
                u = f0[m * 32 + lane]; kc0[2*m] = pk2_(u.x,u.y); kc0[2*m+1] = pk2_(u.z,u.w);
                u = f1[m * 32 + lane]; qc0[2*m] = pk2_(u.x,u.y); qc0[2*m+1] = pk2_(u.z,u.w);
                u = f2[m * 32 + lane]; kc1[2*m] = pk2_(u.x,u.y); kc1[2*m+1] = pk2_(u.z,u.w);
                u = f3[m * 32 + lane]; qc1[2*m] = pk2_(u.x,u.y); qc1[2*m+1] = pk2_(u.z,u.w);
            }
        }
        float4 v0 = *(const float4*)(vp + (size_t)(2 * i) * DIM);
        float4 v1 = *(const float4*)(vp + (size_t)(2 * i + 1) * DIM);
        float2 a2 = *(const float2*)(ap + 2 * i);
        float2 b2 = *(const float2*)(bp + 2 * i);

        unsigned long long zka[4] = {0,0,0,0}, zqa[4] = {0,0,0,0};
        unsigned long long zkb[4] = {0,0,0,0}, zqb[4] = {0,0,0,0};
        unsigned long long c00a = 0, c01a = 0, cka = 0, c11a = 0;
        #pragma unroll
        for (int e = 0; e < 8; e++) {
            #pragma unroll
            for (int r = 0; r < 4; r++) {
                zka[r] = fma2_(z[r][e], kc0[e], zka[r]);
                zqa[r] = fma2_(z[r][e], qc0[e], zqa[r]);
                zkb[r] = fma2_(z[r][e], kc1[e], zkb[r]);
                zqb[r] = fma2_(z[r][e], qc1[e], zqb[r]);
            }
            c00a = fma2_(kc0[e], qc0[e], c00a);
            c01a = fma2_(kc0[e], qc1[e], c01a);
            cka  = fma2_(kc0[e], kc1[e], cka);
            c11a = fma2_(kc1[e], qc1[e], c11a);
        }
        float d[16];
        d[0]=hadd2_(zka[0]); d[1]=hadd2_(zka[1]); d[2]=hadd2_(zka[2]); d[3]=hadd2_(zka[3]);
        d[4]=hadd2_(zkb[0]); d[5]=hadd2_(zkb[1]); d[6]=hadd2_(zkb[2]); d[7]=hadd2_(zkb[3]);
        d[8]=hadd2_(zqa[0]); d[9]=hadd2_(zqa[1]); d[10]=hadd2_(zqa[2]); d[11]=hadd2_(zqa[3]);
        d[12]=hadd2_(zqb[0]); d[13]=hadd2_(zqb[1]); d[14]=hadd2_(zqb[2]); d[15]=hadd2_(zqb[3]);
        float f;
        {
            float x[16];
            #pragma unroll
            for (int j = 0; j < 16; j++) x[j] = d[j] + __shfl_xor_sync(FULL, d[j], 16);
            bool s4 = (lane & 16) != 0;
            float w8[8];
            #pragma unroll
            for (int j = 0; j < 8; j++) w8[j] = s4 ? x[2*j+1] : x[2*j];
            float y8[8];
            #pragma unroll
            for (int j = 0; j < 8; j++) y8[j] = w8[j] + __shfl_xor_sync(FULL, w8[j], 8);
            bool s3 = (lane & 8) != 0;
            float u4[4];
            #pragma unroll
            for (int j = 0; j < 4; j++) u4[j] = s3 ? y8[2*j+1] : y8[2*j];
            float t4[4];
            #pragma unroll
            for (int j = 0; j < 4; j++) t4[j] = u4[j] + __shfl_xor_sync(FULL, u4[j], 4);
            bool s2 = (lane & 4) != 0;
            float sv[2];
            sv[0] = s2 ? t4[1] : t4[0];
            sv[1] = s2 ? t4[3] : t4[2];
            float rv[2];
            rv[0] = sv[0] + __shfl_xor_sync(FULL, sv[0], 2);
            rv[1] = sv[1] + __shfl_xor_sync(FULL, sv[1], 2);
            float qv = (lane & 2) ? rv[1] : rv[0];
            f = qv + __shfl_xor_sync(FULL, qv, 1);
        }
        float c00, c01, ck, c11;
        {
            float e0 = hadd2_(c00a), e1 = hadd2_(c01a), e2 = hadd2_(cka), e3 = hadd2_(c11a);
            float x0 = e0 + __shfl_xor_sync(FULL, e0, 16);
            float x1 = e1 + __shfl_xor_sync(FULL, e1, 16);
            float x2 = e2 + __shfl_xor_sync(FULL, e2, 16);
            float x3 = e3 + __shfl_xor_sync(FULL, e3, 16);
            bool s4 = (lane & 16) != 0;
            float g0 = s4 ? x1 : x0;
            float g1 = s4 ? x3 : x2;
            float y0 = g0 + __shfl_xor_sync(FULL, g0, 8);
            float y1 = g1 + __shfl_xor_sync(FULL, g1, 8);
            float h = (lane & 8) ? y1 : y0;
            h += __shfl_xor_sync(FULL, h, 4);
            h += __shfl_xor_sync(FULL, h, 2);
            h += __shfl_xor_sync(FULL, h, 1);
            c00 = __shfl_sync(FULL, h, 0);
            c01 = __shfl_sync(FULL, h, 16);
            ck  = __shfl_sync(FULL, h, 8);
            c11 = __shfl_sync(FULL, h, 24);
        }
        float zk0r[4], zk1r[4];
        zk0r[0] = __shfl_sync(FULL, f, 0);
        zk0r[1] = __shfl_sync(FULL, f, 16);
        zk0r[2] = __shfl_sync(FULL, f, 8);
        zk0r[3] = __shfl_sync(FULL, f, 24);
        zk1r[0] = __shfl_sync(FULL, f, 4);
        zk1r[1] = __shfl_sync(FULL, f, 20);
        zk1r[2] = __shfl_sync(FULL, f, 12);
        zk1r[3] = __shfl_sync(FULL, f, 28);

        float A1 = A * a2.x;
        float rA1 = 1.0f / A1;
        float ab0 = a2.x * b2.x;
        float vv0[4] = {v0.x, v0.y, v0.z, v0.w};
        float vv1[4] = {v1.x, v1.y, v1.z, v1.w};
        float w0v[4], w1v[4];
        #pragma unroll
        for (int r = 0; r < 4; r++)
            w0v[r] = (b2.x * vv0[r] - ab0 * (A * zk0r[r])) * rA1;
        float A2f = A1 * a2.y;
        float rA2 = 1.0f / A2f;
        float ab1 = a2.y * b2.y;
        #pragma unroll
        for (int r = 0; r < 4; r++) {
            float sk1 = A1 * (zk1r[r] + w0v[r] * ck);
            w1v[r] = (b2.y * vv1[r] - ab1 * sk1) * rA2;
        }

        #pragma unroll
        for (int r = 0; r < 4; r++) {
            unsigned long long W0 = pk2_(w0v[r], w0v[r]);
            unsigned long long W1 = pk2_(w1v[r], w1v[r]);
            #pragma unroll
            for (int e = 0; e < 8; e++)
                z[r][e] = fma2_(W1, kc1[e], fma2_(W0, kc0[e], z[r][e]));
        }

        if (isout) {
            float o;
            if (ostep == 0) o = A1 * (f + w0v[orow] * c00);
            else            o = A2f * (f + w0v[orow] * c01 + w1v[orow] * c11);
            op[(size_t)(2 * i + ostep) * DIM + orow] = o;
        }

        A = A2f;
        if ((i & 7) == 7) {
            unsigned long long AA = pk2_(A, A);
            #pragma unroll
            for (int r = 0; r < 4; r++)
                #pragma unroll
                for (int e = 0; e < 8; e++) z[r][e] = mul2_(z[r][e], AA);
            A = 1.0f;
        }

        cur = (cur == 2) ? 0 : cur + 1;
        nxt = (nxt == 2) ? 0 : nxt + 1;
    }
}

// ---------------- zero-centered RMSNorm * gate -> bf16 hi/lo split -----------
__global__ void __launch_bounds__(128) norm_gate_kernel(
    const float* __restrict__ gdn, const float* __restrict__ norm_w,
    const float* __restrict__ gate, int gstride,
    __nv_bfloat16* __restrict__ fhi, __nv_bfloat16* __restrict__ flo)
{
    __shared__ float rs[4], rq[4];
    const int m = blockIdx.x;
    const int c = threadIdx.x << 2;
    const int lane = threadIdx.x & 31;
    const int warp = threadIdx.x >> 5;

    float4 xv = *(const float4*)(gdn + (size_t)m * DIM + c);
    float s = wredsum_(xv.x + xv.y + xv.z + xv.w);
    float q = wredsum_(xv.x*xv.x + xv.y*xv.y + xv.z*xv.z + xv.w*xv.w);
    if (lane == 0) { rs[warp] = s; rq[warp] = q; }
    __syncthreads();
    float sum = rs[0] + rs[1] + rs[2] + rs[3];
    float sq  = rq[0] + rq[1] + rq[2] + rq[3];
    float mean = sum * (1.0f / DIM);
    float var  = sq * (1.0f / DIM) - mean * mean;
    float inv  = rsqrtf(var + 1e-5f);

    float4 wv = *(const float4*)(norm_w + c);
    float4 gv = *(const float4*)(gate + (size_t)m * gstride + c);
    float r0 = (xv.x - mean) * inv * wv.x * gv.x;
    float r1 = (xv.y - mean) * inv * wv.y * gv.y;
    float r2 = (xv.z - mean) * inv * wv.z * gv.z;
    float r3 = (xv.w - mean) * inv * wv.w * gv.w;

    __nv_bfloat16 h0 = __float2bfloat16(r0), h1 = __float2bfloat16(r1);
    __nv_bfloat16 h2 = __float2bfloat16(r2), h3 = __float2bfloat16(r3);
    __nv_bfloat16 l0 = __float2bfloat16(r0 - __bfloat162float(h0));
    __nv_bfloat16 l1 = __float2bfloat16(r1 - __bfloat162float(h1));
    __nv_bfloat16 l2 = __float2bfloat16(r2 - __bfloat162float(h2));
    __nv_bfloat16 l3 = __float2bfloat16(r3 - __bfloat162float(h3));
    size_t idx = (size_t)m * DIM + c;
    __nv_bfloat162 ph0; ph0.x = h0; ph0.y = h1;
    __nv_bfloat162 ph1; ph1.x = h2; ph1.y = h3;
    __nv_bfloat162 pl0; pl0.x = l0; pl0.y = l1;
    __nv_bfloat162 pl1; pl1.x = l2; pl1.y = l3;
    ((__nv_bfloat162*)(fhi + idx))[0] = ph0;
    ((__nv_bfloat162*)(fhi + idx))[1] = ph1;
    ((__nv_bfloat162*)(flo + idx))[0] = pl0;
    ((__nv_bfloat162*)(flo + idx))[1] = pl1;
}

// ---------------- launch ----------------
extern "C" void kernel_launch(void* const* d_in, const int* in_sizes, int n_in,
                              void* d_out, int out_size) {
    const float* x    = (const float*)d_in[0];
    const float* Wq   = (const float*)d_in[1];
    const float* bq   = (const float*)d_in[2];
    const float* Wk   = (const float*)d_in[3];
    const float* bk   = (const float*)d_in[4];
    const float* Wv   = (const float*)d_in[5];
    const float* bv   = (const float*)d_in[6];
    const float* Wa   = (const float*)d_in[7];
    const float* ba   = (const float*)d_in[8];
    const float* Wb   = (const float*)d_in[9];
    const float* bb   = (const float*)d_in[10];
    const float* cwq  = (const float*)d_in[11];
    const float* cbq  = (const float*)d_in[12];
    const float* cwk  = (const float*)d_in[13];
    const float* cbk  = (const float*)d_in[14];
    const float* cwv  = (const float*)d_in[15];
    const float* cbv  = (const float*)d_in[16];
    const float* norm_w = (const float*)d_in[17];
    const float* Wg   = (const float*)d_in[18];
    const float* bg   = (const float*)d_in[19];
    const float* Wo   = (const float*)d_in[20];
    const float* bo   = (const float*)d_in[21];
    float* out = (float*)d_out;

    float *qkvg, *qn, *kn, *vn, *gdn, *al, *be, *bias4;
    __nv_bfloat16 *xhi, *xlo, *fhi, *flo, *whi, *wlo;
    cudaGetSymbolAddress((void**)&qkvg, g_qkvg);
    cudaGetSymbolAddress((void**)&qn,   g_q);
    cudaGetSymbolAddress((void**)&kn,   g_k);
    cudaGetSymbolAddress((void**)&vn,   g_v);
    cudaGetSymbolAddress((void**)&gdn,  g_gdn);
    cudaGetSymbolAddress((void**)&al,   g_alpha);
    cudaGetSymbolAddress((void**)&be,   g_beta);
    cudaGetSymbolAddress((void**)&bias4, g_bias4);
    cudaGetSymbolAddress((void**)&xhi,  g_xhi);
    cudaGetSymbolAddress((void**)&xlo,  g_xlo);
    cudaGetSymbolAddress((void**)&fhi,  g_fhi);
    cudaGetSymbolAddress((void**)&flo,  g_flo);
    cudaGetSymbolAddress((void**)&whi,  g_whi);
    cudaGetSymbolAddress((void**)&wlo,  g_wlo);

    const int GEMM_SMEM = 2 * 4 * TILEB;  // 81920
    cudaFuncSetAttribute(gemm_mma, cudaFuncAttributeMaxDynamicSharedMemorySize, GEMM_SMEM);

    // launch order: GEMM is launch #4 so ncu's sampler captures it
    pack_bias_kernel<<<NQKVG/256, 256>>>(bq, bk, bv, bg, bias4);            // 1
    convert_split_kernel<<<MTOT*DIM/4/256, 256>>>(x, xhi, xlo, MTOT*DIM/4); // 2
    convert_w4_kernel<<<4*DIM*DIM/4/256, 256>>>(Wq, Wk, Wv, Wg, whi, wlo);  // 3
    dim3 gg4(MTOT/128, NQKVG/128);
    gemm_mma<<<gg4, 256, GEMM_SMEM>>>(xhi, xlo, whi, wlo, bias4, qkvg,      // 4
                                      NQKVG, 3*DIM);

    ab_kernel<<<MTOT / 8, 256>>>(x, Wa, ba, Wb, bb, al, be);
    convert_split_kernel<<<DIM*DIM/4/256, 256>>>(Wo, whi + 4*DIM*DIM, wlo + 4*DIM*DIM, DIM*DIM/4);

    dim3 cg(MTOT, 3);
    conv_fused_kernel<<<cg, 128>>>(qkvg, cwq, cbq, cwk, cbk, cwv, cbv, qn, kn, vn);

    scan_kernel<<<512, 64>>>(qn, kn, vn, al, be, gdn);

    norm_gate_kernel<<<MTOT, 128>>>(gdn, norm_w, qkvg + 1536, NQKVG, fhi, flo);
    dim3 ggo(MTOT/128, DIM/128);
    gemm_mma<<<ggo, 256, GEMM_SMEM>>>(fhi, flo, whi + 4*DIM*DIM, wlo + 4*DIM*DIM,
                                      bo, out, DIM, 1 << 30);
}